// round 7
// baseline (speedup 1.0000x reference)
#include <cuda_runtime.h>
#include <cstdint>

#define Bb  8
#define Kk  64
#define Ll  1024
#define Hh  256
#define FFN 3072
#define WIN 20
#define F   32
#define NCH (FFN / F)   // 96

// scratch (device globals — no runtime allocation allowed)
__device__ __align__(16) float    g_ctx[Bb * Kk * Hh];   // [B*K, H] window max
__device__ __align__(16) float    g_ph [Bb * Kk * FFN];  // head @ W1a + b1
__device__ __align__(16) float    g_pt [Bb * Kk * FFN];  // tail @ W1b
__device__ __align__(16) uint32_t g_w1t[FFN * Hh];       // W1 ctx block transposed [n=3072][k=256] tf32, k-pair-permuted
__device__ __align__(16) uint32_t g_w2c[FFN * Hh];       // W2 [k=3072][n=256] tf32 (plain convert, unpermuted)

// permutation within each k-octet: logical k -> (k&3)*2 + (k>>2)  (pairs (q,q+4) adjacent)
__device__ __forceinline__ int kperm(int k) { return (k & ~7) | (((k & 3) << 1) | ((k >> 2) & 1)); }

__device__ __forceinline__ uint32_t f2tf(float f) {
    uint32_t r;
    asm("cvt.rna.tf32.f32 %0, %1;" : "=r"(r) : "f"(f));
    return r;
}

__device__ __forceinline__ void mma8(float d[4], const uint32_t a[4], const uint32_t b[2]) {
    asm volatile(
        "mma.sync.aligned.m16n8k8.row.col.f32.tf32.tf32.f32 "
        "{%0,%1,%2,%3}, {%4,%5,%6,%7}, {%8,%9}, {%0,%1,%2,%3};"
        : "+f"(d[0]), "+f"(d[1]), "+f"(d[2]), "+f"(d[3])
        : "r"(a[0]), "r"(a[1]), "r"(a[2]), "r"(a[3]), "r"(b[0]), "r"(b[1]));
}

__device__ __forceinline__ void cp16(uint32_t dst_smem, const void* src) {
    asm volatile("cp.async.cg.shared.global [%0], [%1], 16;" :: "r"(dst_smem), "l"(src));
}
__device__ __forceinline__ void cp_commit() { asm volatile("cp.async.commit_group;"); }
template <int N> __device__ __forceinline__ void cp_wait() {
    asm volatile("cp.async.wait_group %0;" :: "n"(N));
}

// ---------------------------------------------------------------------------
// Kernel 1: per-span window max over token_reps. grid = B*K, 256 threads.
// ---------------------------------------------------------------------------
__global__ void ctx_kernel(const float* __restrict__ tok,
                           const int* __restrict__ ids) {
    int bk = blockIdx.x;
    int b  = bk >> 6;
    int h  = threadIdx.x;
    int s  = ids[bk * 2 + 0];
    int e  = ids[bk * 2 + 1];

    float m = __int_as_float(0xff800000);

    int lo = s - WIN; if (lo < 0) lo = 0;
    for (int p = lo; p < s; ++p)
        m = fmaxf(m, tok[((size_t)b * Ll + p) * Hh + h]);

    int hi = e + WIN; if (hi > Ll - 1) hi = Ll - 1;
    for (int p = e + 1; p <= hi; ++p)
        m = fmaxf(m, tok[((size_t)b * Ll + p) * Hh + h]);

    g_ctx[(size_t)bk * Hh + h] = m;
}

// ---------------------------------------------------------------------------
// Prep A: transpose+convert W1 ctx block -> g_w1t[n][kperm] tf32. grid (96,8), blk (32,8)
// ---------------------------------------------------------------------------
__global__ void w1t_kernel(const float* __restrict__ W1) {
    __shared__ float tile[32][33];
    int n0 = blockIdx.x * 32, k0 = blockIdx.y * 32;
    int tx = threadIdx.x, ty = threadIdx.y;
#pragma unroll
    for (int r = 0; r < 4; ++r) {
        int k = ty + r * 8;
        tile[tx][k] = W1[(size_t)(512 + k0 + k) * FFN + n0 + tx];
    }
    __syncthreads();
#pragma unroll
    for (int r = 0; r < 4; ++r) {
        int n = ty + r * 8;
        g_w1t[(size_t)(n0 + n) * 256 + k0 + kperm(tx)] = f2tf(tile[n][tx]);
    }
}

// Prep B: convert W2 -> tf32, layout [k=3072][n=256] (no transpose, no perm).
__global__ void w2c_kernel(const float* __restrict__ W2) {
    int i = blockIdx.x * 256 + threadIdx.x;   // float4 index
    float4 v = ((const float4*)W2)[i];
    uint32_t t[4] = {f2tf(v.x), f2tf(v.y), f2tf(v.z), f2tf(v.w)};
    ((uint4*)g_w2c)[i] = *(uint4*)t;
}

// ---------------------------------------------------------------------------
// Kernel 2: Ph = cand @ W1[0:256] + b1 ; Pt = cand @ W1[256:512]  (mma.sync)
// ---------------------------------------------------------------------------
__global__ __launch_bounds__(128) void phpt_kernel(const float* __restrict__ cand,
                                                   const float* __restrict__ W1,
                                                   const float* __restrict__ b1) {
    __shared__ uint32_t a_s[64 * 68];
    __shared__ uint32_t b_s[64 * 68];

    int tid = threadIdx.x;
    int w = tid >> 5, lane = tid & 31;
    int g = lane >> 2, q = lane & 3;
    int wm = w >> 1, wn = w & 1;
    int n0 = blockIdx.x * 64;
    int m0 = blockIdx.y * 64;
    int s  = blockIdx.z;

    float acc[2][4][4];
#pragma unroll
    for (int mt = 0; mt < 2; ++mt)
#pragma unroll
        for (int nt = 0; nt < 4; ++nt)
#pragma unroll
            for (int r = 0; r < 4; ++r) acc[mt][nt][r] = 0.f;

    for (int kc = 0; kc < 256; kc += 64) {
        __syncthreads();
#pragma unroll
        for (int it = 0; it < 8; ++it) {
            int idx = it * 128 + tid;
            int m = idx >> 4, c4 = (idx & 15) << 2;
            float4 v = *(const float4*)&cand[(size_t)(m0 + m) * 256 + kc + c4];
            uint32_t* dst = &a_s[m * 68 + c4];
            dst[0] = f2tf(v.x); dst[1] = f2tf(v.y); dst[2] = f2tf(v.z); dst[3] = f2tf(v.w);
        }
#pragma unroll
        for (int it = 0; it < 8; ++it) {
            int idx = it * 128 + tid;
            int kk = idx >> 4, n4 = (idx & 15) << 2;
            float4 v = *(const float4*)&W1[(size_t)(s * 256 + kc + kk) * FFN + n0 + n4];
            b_s[(n4 + 0) * 68 + kk] = f2tf(v.x);
            b_s[(n4 + 1) * 68 + kk] = f2tf(v.y);
            b_s[(n4 + 2) * 68 + kk] = f2tf(v.z);
            b_s[(n4 + 3) * 68 + kk] = f2tf(v.w);
        }
        __syncthreads();

#pragma unroll
        for (int ks = 0; ks < 64; ks += 8) {
            uint32_t a[2][4], bb[4][2];
#pragma unroll
            for (int mt = 0; mt < 2; ++mt) {
                int r = wm * 32 + mt * 16 + g;
                a[mt][0] = a_s[r * 68 + ks + q];
                a[mt][1] = a_s[(r + 8) * 68 + ks + q];
                a[mt][2] = a_s[r * 68 + ks + q + 4];
                a[mt][3] = a_s[(r + 8) * 68 + ks + q + 4];
            }
#pragma unroll
            for (int nt = 0; nt < 4; ++nt) {
                int c = wn * 32 + nt * 8 + g;
                bb[nt][0] = b_s[c * 68 + ks + q];
                bb[nt][1] = b_s[c * 68 + ks + q + 4];
            }
#pragma unroll
            for (int mt = 0; mt < 2; ++mt)
#pragma unroll
                for (int nt = 0; nt < 4; ++nt)
                    mma8(acc[mt][nt], a[mt], bb[nt]);
        }
    }

    float* out = s ? g_pt : g_ph;
#pragma unroll
    for (int mt = 0; mt < 2; ++mt) {
#pragma unroll
        for (int nt = 0; nt < 4; ++nt) {
            int r0 = m0 + wm * 32 + mt * 16 + g;
            int c0 = n0 + wn * 32 + nt * 8 + 2 * q;
            float bias0 = s ? 0.f : b1[c0];
            float bias1 = s ? 0.f : b1[c0 + 1];
            float2 v0 = make_float2(acc[mt][nt][0] + bias0, acc[mt][nt][1] + bias1);
            float2 v1 = make_float2(acc[mt][nt][2] + bias0, acc[mt][nt][3] + bias1);
            *(float2*)&out[(size_t)r0 * FFN + c0] = v0;
            *(float2*)&out[(size_t)(r0 + 8) * FFN + c0] = v1;
        }
    }
}

// ---------------------------------------------------------------------------
// Kernel 3: warp-specialized fused pairwise kernel. 256 threads / 8 warps.
// Per iter c (F=32 chunk):
//   warps 0-3: GEMM1(c)  [64x32 = 2x2 warp grid] + epilogue -> hs[c&1]
//   warps 4-7: GEMM2(c-1)[64x256 = 2x2 warp grid], oacc in registers
// Schedule per iter: cp.wait_group 0 -> syncthreads -> stage{w1(c+1),w2(c)} -> compute
// SMEM (words): ctxA 64x264 | w1b 2x(32x264) | w2b 2x(32x264) | hs 2x(64x40)
// total 55808 words = 223232 B
// ---------------------------------------------------------------------------
#define CTXA_W 0
#define W1B0_W 16896
#define W1B1_W 25344
#define W2B0_W 33792
#define W2B1_W 42240
#define HS0_W  50688
#define HS1_W  53248
#define SMEM_WORDS 55808

__global__ __launch_bounds__(256, 1) void pair_kernel(const float* __restrict__ b2,
                                                      float* __restrict__ out) {
    extern __shared__ __align__(16) uint32_t sm[];
    uint32_t* ctxA = sm + CTXA_W;
    uint32_t* w1b[2] = { sm + W1B0_W, sm + W1B1_W };
    uint32_t* w2b[2] = { sm + W2B0_W, sm + W2B1_W };
    uint32_t* hsb[2] = { sm + HS0_W,  sm + HS1_W };

    uint32_t w1u[2] = { (uint32_t)__cvta_generic_to_shared(w1b[0]),
                        (uint32_t)__cvta_generic_to_shared(w1b[1]) };
    uint32_t w2u[2] = { (uint32_t)__cvta_generic_to_shared(w2b[0]),
                        (uint32_t)__cvta_generic_to_shared(w2b[1]) };

    int tid = threadIdx.x;
    int w = tid >> 5, lane = tid & 31;
    int g = lane >> 2, q = lane & 3;
    int b  = blockIdx.z;
    int I0 = blockIdx.y * 8;
    int J0 = blockIdx.x * 8;
    int p0 = ((q & 1) << 2) | (q >> 1);   // stored offset of logical col 2q within octet

    const float* phbase = g_ph + (size_t)(b * Kk + I0) * FFN;
    const float* ptbase = g_pt + (size_t)(b * Kk + J0) * FFN;

    // staging: 2048 cp16 each (8 per thread)
    auto stage_w1 = [&](int buf, int fc) {
#pragma unroll
        for (int i = 0; i < 8; ++i) {
            int idx = i * 256 + tid;
            int n = idx >> 6, k4 = (idx & 63) << 2;
            cp16(w1u[buf] + (uint32_t)(n * 264 + k4) * 4,
                 g_w1t + (size_t)(fc + n) * 256 + k4);
        }
    };
    auto stage_w2 = [&](int buf, int fc) {
#pragma unroll
        for (int i = 0; i < 8; ++i) {
            int idx = i * 256 + tid;
            int k = idx >> 6, n4 = (idx & 63) << 2;
            cp16(w2u[buf] + (uint32_t)(k * 264 + n4) * 4,
                 g_w2c + (size_t)(fc + k) * 256 + n4);
        }
    };

    // build ctxA[r][kperm(c)] = tf32(max(ctx_i, ctx_j)), r = ii*8 + jj, stride 264
    const float* ctxb = g_ctx + (size_t)b * Kk * Hh;
    for (int idx = tid; idx < 64 * 64; idx += 256) {
        int r = idx >> 6, k4 = (idx & 63) << 2;
        float4 va = *(const float4*)&ctxb[(I0 + (r >> 3)) * 256 + k4];
        float4 vb = *(const float4*)&ctxb[(J0 + (r & 7)) * 256 + k4];
        uint32_t t[4] = { f2tf(fmaxf(va.x, vb.x)), f2tf(fmaxf(va.y, vb.y)),
                          f2tf(fmaxf(va.z, vb.z)), f2tf(fmaxf(va.w, vb.w)) };
        int base = r * 264 + (k4 & ~7) + ((k4 & 4) ? 1 : 0);
#pragma unroll
        for (int i = 0; i < 4; ++i) ctxA[base + 2 * i] = t[i];
    }

    // prologue: stage w1(0)
    stage_w1(0, 0); cp_commit();

    // role indices
    int wm1 = w >> 1, wn1 = w & 1;          // GEMM1 warps 0-3 (wm1 in 0..1)
    int wq  = w - 4;
    int wm2 = (wq >> 1) & 1, wn2 = wq & 1;  // GEMM2 warps 4-7

    float oacc[2][16][4];                   // GEMM2 warps only (dead regs for 0-3)
#pragma unroll
    for (int mt = 0; mt < 2; ++mt)
#pragma unroll
        for (int nt = 0; nt < 16; ++nt)
#pragma unroll
            for (int r = 0; r < 4; ++r) oacc[mt][nt][r] = 0.f;

    for (int c = 0; c <= NCH; ++c) {
        cp_wait<0>();          // all staged data for this iter landed (mine)
        __syncthreads();       // everyone's cp done+visible; prev compute done; hs visible

        // stage next: G_c = { w1(c+1), w2(c) }
        if (c + 1 < NCH) stage_w1((c + 1) & 1, (c + 1) * F);
        if (c < NCH)     stage_w2(c & 1, c * F);
        cp_commit();

        if (w < 4) {
            // ---- GEMM1(c): rows wm1*32 (2 m-tiles), cols wn1*16 (2 n-tiles), K=256
            if (c < NCH) {
                int fc = c * F;
                const uint32_t* w1c = w1b[c & 1];
                uint32_t* hsc = hsb[c & 1];

                // prefetch ph/pt (L2)
                float2 phv[2][2][2], ptv[2];
#pragma unroll
                for (int mt = 0; mt < 2; ++mt) {
                    int ii = 4 * wm1 + 2 * mt;
#pragma unroll
                    for (int nt = 0; nt < 2; ++nt) {
                        int col = fc + wn1 * 16 + nt * 8 + 2 * q;
                        phv[mt][0][nt] = __ldg((const float2*)&phbase[(size_t)ii * FFN + col]);
                        phv[mt][1][nt] = __ldg((const float2*)&phbase[(size_t)(ii + 1) * FFN + col]);
                    }
                }
#pragma unroll
                for (int nt = 0; nt < 2; ++nt)
                    ptv[nt] = __ldg((const float2*)&ptbase[(size_t)g * FFN + fc + wn1 * 16 + nt * 8 + 2 * q]);

                float c1[2][2][4];
#pragma unroll
                for (int mt = 0; mt < 2; ++mt)
#pragma unroll
                    for (int nt = 0; nt < 2; ++nt)
#pragma unroll
                        for (int r = 0; r < 4; ++r) c1[mt][nt][r] = 0.f;

#pragma unroll
                for (int ks = 0; ks < 256; ks += 8) {
                    uint2 av[2][2], bv[2];
#pragma unroll
                    for (int mt = 0; mt < 2; ++mt) {
                        int r = wm1 * 32 + mt * 16 + g;
                        av[mt][0] = *(const uint2*)&ctxA[r * 264 + ks + 2 * q];
                        av[mt][1] = *(const uint2*)&ctxA[(r + 8) * 264 + ks + 2 * q];
                    }
#pragma unroll
                    for (int nt = 0; nt < 2; ++nt) {
                        int cc = wn1 * 16 + nt * 8 + g;
                        bv[nt] = *(const uint2*)&w1c[cc * 264 + ks + 2 * q];
                    }
#pragma unroll
                    for (int mt = 0; mt < 2; ++mt)
#pragma unroll
                        for (int nt = 0; nt < 2; ++nt) {
                            uint32_t a[4] = { av[mt][0].x, av[mt][1].x, av[mt][0].y, av[mt][1].y };
                            uint32_t bb[2] = { bv[nt].x, bv[nt].y };
                            mma8(c1[mt][nt], a, bb);
                        }
                }

                // epilogue -> hs[c&1], k-pair-permuted columns
#pragma unroll
                for (int mt = 0; mt < 2; ++mt) {
                    int r = wm1 * 32 + mt * 16 + g;
#pragma unroll
                    for (int nt = 0; nt < 2; ++nt) {
                        int cb = wn1 * 16 + nt * 8 + p0;
                        float2 ph0 = phv[mt][0][nt];
                        float2 ph1 = phv[mt][1][nt];
                        float2 pt  = ptv[nt];
                        hsc[r * 40 + cb]           = f2tf(fmaxf(c1[mt][nt][0] + ph0.x + pt.x, 0.f));
                        hsc[r * 40 + cb + 2]       = f2tf(fmaxf(c1[mt][nt][1] + ph0.y + pt.y, 0.f));
                        hsc[(r + 8) * 40 + cb]     = f2tf(fmaxf(c1[mt][nt][2] + ph1.x + pt.x, 0.f));
                        hsc[(r + 8) * 40 + cb + 2] = f2tf(fmaxf(c1[mt][nt][3] + ph1.y + pt.y, 0.f));
                    }
                }
            }
        } else {
            // ---- GEMM2(c-1): rows wm2*32 (2 m-tiles), cols wn2*128 (16 n-tiles), K=32
            if (c > 0) {
                const uint32_t* hsp = hsb[(c - 1) & 1];
                const uint32_t* w2p = w2b[(c - 1) & 1];
#pragma unroll
                for (int ks = 0; ks < 32; ks += 8) {
                    uint2 av[2][2];
#pragma unroll
                    for (int mt = 0; mt < 2; ++mt) {
                        int r = wm2 * 32 + mt * 16 + g;
                        av[mt][0] = *(const uint2*)&hsp[r * 40 + ks + 2 * q];
                        av[mt][1] = *(const uint2*)&hsp[(r + 8) * 40 + ks + 2 * q];
                    }
#pragma unroll
                    for (int nt = 0; nt < 16; ++nt) {
                        int cc = wn2 * 128 + nt * 8 + g;
                        uint32_t bb[2];
                        bb[0] = w2p[(ks + q) * 264 + cc];
                        bb[1] = w2p[(ks + q + 4) * 264 + cc];
#pragma unroll
                        for (int mt = 0; mt < 2; ++mt) {
                            uint32_t a[4] = { av[mt][0].x, av[mt][1].x, av[mt][0].y, av[mt][1].y };
                            mma8(oacc[mt][nt], a, bb);
                        }
                    }
                }
            }
        }
    }

    // ---- final output (GEMM2 warps hold oacc) ----
    if (w >= 4) {
        float* outp = out + (size_t)b * (Kk * Kk * Hh);
#pragma unroll
        for (int mt = 0; mt < 2; ++mt) {
            int r = wm2 * 32 + mt * 16 + g;
            int pA = (I0 + (r >> 3)) * 64 + (J0 + (r & 7));
            int pB = (I0 + ((r + 8) >> 3)) * 64 + (J0 + ((r + 8) & 7));
#pragma unroll
            for (int nt = 0; nt < 16; ++nt) {
                int c0 = wn2 * 128 + nt * 8 + 2 * q;
                float2 bv = __ldg((const float2*)&b2[c0]);
                float2 v0 = make_float2(oacc[mt][nt][0] + bv.x, oacc[mt][nt][1] + bv.y);
                float2 v1 = make_float2(oacc[mt][nt][2] + bv.x, oacc[mt][nt][3] + bv.y);
                *(float2*)&outp[(size_t)pA * 256 + c0] = v0;
                *(float2*)&outp[(size_t)pB * 256 + c0] = v1;
            }
        }
    }
}

// ---------------------------------------------------------------------------
extern "C" void kernel_launch(void* const* d_in, const int* in_sizes, int n_in,
                              void* d_out, int out_size) {
    const float* cand = (const float*)d_in[0];
    const float* tok  = (const float*)d_in[1];
    const float* W1   = (const float*)d_in[2];
    const float* b1   = (const float*)d_in[3];
    const float* W2   = (const float*)d_in[4];
    const float* b2   = (const float*)d_in[5];
    const int*   ids  = (const int*)d_in[6];
    float* out = (float*)d_out;

    ctx_kernel<<<Bb * Kk, Hh>>>(tok, ids);
    w1t_kernel<<<dim3(FFN / 32, 256 / 32), dim3(32, 8)>>>(W1);
    w2c_kernel<<<(FFN * Hh) / (256 * 4), 256>>>(W2);
    phpt_kernel<<<dim3(FFN / 64, (Bb * Kk) / 64, 2), 128>>>(cand, W1, b1);

    const int smem_bytes = SMEM_WORDS * 4;  // 223232
    cudaFuncSetAttribute(pair_kernel, cudaFuncAttributeMaxDynamicSharedMemorySize, smem_bytes);
    pair_kernel<<<dim3(8, 8, 8), 256, smem_bytes>>>(b2, out);
}

// round 8
// speedup vs baseline: 1.1070x; 1.1070x over previous
#include <cuda_runtime.h>
#include <cstdint>

#define Bb  8
#define Kk  64
#define Ll  1024
#define Hh  256
#define FFN 3072
#define WIN 20

// scratch (device globals — no runtime allocation allowed)
__device__ __align__(16) float    g_ctx[Bb * Kk * Hh];   // [B*K, H] window max
__device__ __align__(16) float    g_ph [Bb * Kk * FFN];  // head @ W1a + b1
__device__ __align__(16) float    g_pt [Bb * Kk * FFN];  // tail @ W1b
__device__ __align__(16) uint32_t g_w1t[FFN * Hh];       // W1 ctx block transposed [n=3072][k=256] tf32
__device__ __align__(16) uint32_t g_w2t[FFN * Hh];       // W2 [k=3072][n=256] tf32

__device__ __forceinline__ uint32_t f2tf(float f) {
    uint32_t r;
    asm("cvt.rna.tf32.f32 %0, %1;" : "=r"(r) : "f"(f));
    return r;
}

__device__ __forceinline__ void mma8(float d[4], const uint32_t a[4], const uint32_t b[2]) {
    asm volatile(
        "mma.sync.aligned.m16n8k8.row.col.f32.tf32.tf32.f32 "
        "{%0,%1,%2,%3}, {%4,%5,%6,%7}, {%8,%9}, {%0,%1,%2,%3};"
        : "+f"(d[0]), "+f"(d[1]), "+f"(d[2]), "+f"(d[3])
        : "r"(a[0]), "r"(a[1]), "r"(a[2]), "r"(a[3]), "r"(b[0]), "r"(b[1]));
}

__device__ __forceinline__ void cp16(uint32_t dst_smem, const void* src) {
    asm volatile("cp.async.cg.shared.global [%0], [%1], 16;" :: "r"(dst_smem), "l"(src));
}
__device__ __forceinline__ void cp_commit() { asm volatile("cp.async.commit_group;"); }
template <int N> __device__ __forceinline__ void cp_wait() {
    asm volatile("cp.async.wait_group %0;" :: "n"(N));
}

// ---------------------------------------------------------------------------
// Kernel 1: per-span window max over token_reps. grid = B*K, 256 threads.
// ---------------------------------------------------------------------------
__global__ void ctx_kernel(const float* __restrict__ tok,
                           const int* __restrict__ ids) {
    int bk = blockIdx.x;
    int b  = bk >> 6;
    int h  = threadIdx.x;
    int s  = ids[bk * 2 + 0];
    int e  = ids[bk * 2 + 1];

    float m = __int_as_float(0xff800000);

    int lo = s - WIN; if (lo < 0) lo = 0;
    for (int p = lo; p < s; ++p)
        m = fmaxf(m, tok[((size_t)b * Ll + p) * Hh + h]);

    int hi = e + WIN; if (hi > Ll - 1) hi = Ll - 1;
    for (int p = e + 1; p <= hi; ++p)
        m = fmaxf(m, tok[((size_t)b * Ll + p) * Hh + h]);

    g_ctx[(size_t)bk * Hh + h] = m;
}

// ---------------------------------------------------------------------------
// Prep A: transpose+convert W1 ctx block -> g_w1t[n][k] tf32. grid (96,8), blk (32,8)
// ---------------------------------------------------------------------------
__global__ void w1t_kernel(const float* __restrict__ W1) {
    __shared__ float tile[32][33];
    int n0 = blockIdx.x * 32, k0 = blockIdx.y * 32;
    int tx = threadIdx.x, ty = threadIdx.y;
#pragma unroll
    for (int r = 0; r < 4; ++r) {
        int k = ty + r * 8;
        tile[tx][k] = W1[(size_t)(512 + k0 + k) * FFN + n0 + tx];
    }
    __syncthreads();
#pragma unroll
    for (int r = 0; r < 4; ++r) {
        int n = ty + r * 8;
        g_w1t[(size_t)(n0 + n) * 256 + k0 + tx] = f2tf(tile[n][tx]);
    }
}

// Prep B: convert W2 -> tf32, layout [k=3072][n=256]. grid 768, 256 thr.
__global__ void w2t_kernel(const float* __restrict__ W2) {
    int i = blockIdx.x * 256 + threadIdx.x;   // float4 index
    float4 v = ((const float4*)W2)[i];
    uint32_t t[4] = {f2tf(v.x), f2tf(v.y), f2tf(v.z), f2tf(v.w)};
    ((uint4*)g_w2t)[i] = *(uint4*)t;
}

// ---------------------------------------------------------------------------
// Kernel 2: Ph = cand @ W1[0:256] + b1 ; Pt = cand @ W1[256:512]  (mma.sync)
// ---------------------------------------------------------------------------
__global__ __launch_bounds__(128) void phpt_kernel(const float* __restrict__ cand,
                                                   const float* __restrict__ W1,
                                                   const float* __restrict__ b1) {
    __shared__ uint32_t a_s[64 * 68];
    __shared__ uint32_t b_s[64 * 68];

    int tid = threadIdx.x;
    int w = tid >> 5, lane = tid & 31;
    int g = lane >> 2, q = lane & 3;
    int wm = w >> 1, wn = w & 1;
    int n0 = blockIdx.x * 64;
    int m0 = blockIdx.y * 64;
    int s  = blockIdx.z;

    float acc[2][4][4];
#pragma unroll
    for (int mt = 0; mt < 2; ++mt)
#pragma unroll
        for (int nt = 0; nt < 4; ++nt)
#pragma unroll
            for (int r = 0; r < 4; ++r) acc[mt][nt][r] = 0.f;

    for (int kc = 0; kc < 256; kc += 64) {
        __syncthreads();
#pragma unroll
        for (int it = 0; it < 8; ++it) {
            int idx = it * 128 + tid;
            int m = idx >> 4, c4 = (idx & 15) << 2;
            float4 v = *(const float4*)&cand[(size_t)(m0 + m) * 256 + kc + c4];
            uint32_t* dst = &a_s[m * 68 + c4];
            dst[0] = f2tf(v.x); dst[1] = f2tf(v.y); dst[2] = f2tf(v.z); dst[3] = f2tf(v.w);
        }
#pragma unroll
        for (int it = 0; it < 8; ++it) {
            int idx = it * 128 + tid;
            int kk = idx >> 4, n4 = (idx & 15) << 2;
            float4 v = *(const float4*)&W1[(size_t)(s * 256 + kc + kk) * FFN + n0 + n4];
            b_s[(n4 + 0) * 68 + kk] = f2tf(v.x);
            b_s[(n4 + 1) * 68 + kk] = f2tf(v.y);
            b_s[(n4 + 2) * 68 + kk] = f2tf(v.z);
            b_s[(n4 + 3) * 68 + kk] = f2tf(v.w);
        }
        __syncthreads();

#pragma unroll
        for (int ks = 0; ks < 64; ks += 8) {
            uint32_t a[2][4], bb[4][2];
#pragma unroll
            for (int mt = 0; mt < 2; ++mt) {
                int r = wm * 32 + mt * 16 + g;
                a[mt][0] = a_s[r * 68 + ks + q];
                a[mt][1] = a_s[(r + 8) * 68 + ks + q];
                a[mt][2] = a_s[r * 68 + ks + q + 4];
                a[mt][3] = a_s[(r + 8) * 68 + ks + q + 4];
            }
#pragma unroll
            for (int nt = 0; nt < 4; ++nt) {
                int c = wn * 32 + nt * 8 + g;
                bb[nt][0] = b_s[c * 68 + ks + q];
                bb[nt][1] = b_s[c * 68 + ks + q + 4];
            }
#pragma unroll
            for (int mt = 0; mt < 2; ++mt)
#pragma unroll
                for (int nt = 0; nt < 4; ++nt)
                    mma8(acc[mt][nt], a[mt], bb[nt]);
        }
    }

    float* out = s ? g_pt : g_ph;
#pragma unroll
    for (int mt = 0; mt < 2; ++mt) {
#pragma unroll
        for (int nt = 0; nt < 4; ++nt) {
            int r0 = m0 + wm * 32 + mt * 16 + g;
            int c0 = n0 + wn * 32 + nt * 8 + 2 * q;
            float bias0 = s ? 0.f : b1[c0];
            float bias1 = s ? 0.f : b1[c0 + 1];
            float2 v0 = make_float2(acc[mt][nt][0] + bias0, acc[mt][nt][1] + bias1);
            float2 v1 = make_float2(acc[mt][nt][2] + bias0, acc[mt][nt][3] + bias1);
            *(float2*)&out[(size_t)r0 * FFN + c0] = v0;
            *(float2*)&out[(size_t)(r0 + 8) * FFN + c0] = v1;
        }
    }
}

// ---------------------------------------------------------------------------
// Kernel 3: fused pairwise kernel (R3 layouts/grids; rescheduled + pipelined).
// 256 threads / 8 warps (2m x 4n). Per chunk (F=64):
//   wait W1 -> sync -> GEMM1 (K=256, 2-stage frag pipeline) -> epi -> hs
//   wait W2 -> sync -> stage W1(c+1)+phpt(c+1) -> GEMM2 (pipelined)
//   sync -> stage W2(c+1)
// SMEM (words): ctxA 64x260 | w1b 64x260 | w2s 64x264 | hs 64x68
//               | phs 512 | pts 512 | b2s 256   = 55808 words (223232 B)
// ---------------------------------------------------------------------------
#define CTXA_W 0
#define W1B_W  16640
#define W2S_W  33280
#define HS_W   50176
#define PHS_W  54528
#define PTS_W  55040
#define B2S_W  55552
#define SMEM_WORDS 55808

__global__ __launch_bounds__(256, 1) void pair_kernel(const float* __restrict__ b2,
                                                      float* __restrict__ out) {
    extern __shared__ __align__(16) uint32_t sm[];
    uint32_t* ctxA = sm + CTXA_W;
    uint32_t* w1b  = sm + W1B_W;
    uint32_t* w2s  = sm + W2S_W;
    uint32_t* hs   = sm + HS_W;
    float*    phs  = (float*)(sm + PHS_W);
    float*    pts  = (float*)(sm + PTS_W);
    float*    b2s  = (float*)(sm + B2S_W);

    const uint32_t w1b_u = (uint32_t)__cvta_generic_to_shared(w1b);
    const uint32_t w2s_u = (uint32_t)__cvta_generic_to_shared(w2s);
    const uint32_t phs_u = (uint32_t)__cvta_generic_to_shared(phs);
    const uint32_t pts_u = (uint32_t)__cvta_generic_to_shared(pts);

    int tid = threadIdx.x;
    int w = tid >> 5, lane = tid & 31;
    int g = lane >> 2, q = lane & 3;
    int wm = w >> 2;    // 0..1
    int wn = w & 3;     // 0..3
    int b  = blockIdx.z;
    int I0 = blockIdx.y * 8;
    int J0 = blockIdx.x * 8;

    const float* phbase = g_ph + (size_t)(b * Kk + I0) * FFN;
    const float* ptbase = g_pt + (size_t)(b * Kk + J0) * FFN;

    // --- staging helpers ---
    auto stage_w1 = [&](int fc) {              // [64 n][256 k], stride 260
#pragma unroll
        for (int i = 0; i < 16; ++i) {
            int idx = i * 256 + tid;           // 4096 x 16B
            int n = idx >> 6, k4 = (idx & 63) << 2;
            cp16(w1b_u + (uint32_t)(n * 260 + k4) * 4,
                 g_w1t + (size_t)(fc + n) * 256 + k4);
        }
    };
    auto stage_w2 = [&](int fc) {              // [64 k][256 n], stride 264
#pragma unroll
        for (int i = 0; i < 16; ++i) {
            int idx = i * 256 + tid;           // 4096 x 16B
            int k = idx >> 6, n4 = (idx & 63) << 2;
            cp16(w2s_u + (uint32_t)(k * 264 + n4) * 4,
                 g_w2t + (size_t)(fc + k) * 256 + n4);
        }
    };
    auto stage_phpt = [&](int fc) {            // ph/pt [8][64]
        if (tid < 128) {
            int row = tid >> 4, c4 = (tid & 15) << 2;
            cp16(phs_u + (uint32_t)(row * 64 + c4) * 4,
                 phbase + (size_t)row * FFN + fc + c4);
        } else {
            int t = tid - 128;
            int row = t >> 4, c4 = (t & 15) << 2;
            cp16(pts_u + (uint32_t)(row * 64 + c4) * 4,
                 ptbase + (size_t)row * FFN + fc + c4);
        }
    };

    b2s[tid] = b2[tid];

    // prefetch chunk 0: G1 = {w1, ph/pt}, G2 = {w2}
    stage_w1(0); stage_phpt(0); cp_commit();
    stage_w2(0);                cp_commit();

    // build ctxA[r][c] = tf32(max(ctx_i, ctx_j)), r = ii*8 + jj, stride 260
    const float* ctxb = g_ctx + (size_t)b * Kk * Hh;
    for (int idx = tid; idx < 64 * 64; idx += 256) {
        int r = idx >> 6, k4 = (idx & 63) << 2;
        float4 va = *(const float4*)&ctxb[(I0 + (r >> 3)) * 256 + k4];
        float4 vb = *(const float4*)&ctxb[(J0 + (r & 7)) * 256 + k4];
        uint32_t* dst = &ctxA[r * 260 + k4];
        dst[0] = f2tf(fmaxf(va.x, vb.x));
        dst[1] = f2tf(fmaxf(va.y, vb.y));
        dst[2] = f2tf(fmaxf(va.z, vb.z));
        dst[3] = f2tf(fmaxf(va.w, vb.w));
    }

    float oacc[2][8][4];
#pragma unroll
    for (int mt = 0; mt < 2; ++mt)
#pragma unroll
        for (int nt = 0; nt < 8; ++nt)
#pragma unroll
            for (int r = 0; r < 4; ++r) oacc[mt][nt][r] = 0.f;

    const int rA0 = wm * 32 + g;              // GEMM1/2 row anchors
    const int cB0 = wn * 16 + g;              // GEMM1 col anchor

    for (int c48 = 0; c48 < 48; ++c48) {
        int fc  = c48 * 64;
        int fcn = (c48 < 47) ? fc + 64 : 0;   // harmless redundant prefetch on last iter

        cp_wait<1>();          // G1_c landed (w1 + ph/pt)
        __syncthreads();       // + ctxA/hs hazards from previous iteration

        // ---- GEMM1: K=256, 2-stage fragment pipeline ----
        float c1[2][2][4];
#pragma unroll
        for (int mt = 0; mt < 2; ++mt)
#pragma unroll
            for (int nt = 0; nt < 2; ++nt)
#pragma unroll
                for (int r = 0; r < 4; ++r) c1[mt][nt][r] = 0.f;

        uint32_t af[2][2][4], bf[2][2][2];
        // load ks=0 into buf 0
#pragma unroll
        for (int mt = 0; mt < 2; ++mt) {
            int r = rA0 + mt * 16;
            af[0][mt][0] = ctxA[r * 260 + q];
            af[0][mt][1] = ctxA[(r + 8) * 260 + q];
            af[0][mt][2] = ctxA[r * 260 + q + 4];
            af[0][mt][3] = ctxA[(r + 8) * 260 + q + 4];
        }
#pragma unroll
        for (int nt = 0; nt < 2; ++nt) {
            int cc = cB0 + nt * 8;
            bf[0][nt][0] = w1b[cc * 260 + q];
            bf[0][nt][1] = w1b[cc * 260 + q + 4];
        }

#pragma unroll
        for (int i = 0; i < 32; ++i) {
            int cur = i & 1;
            if (i < 31) {
                int kk = (i + 1) * 8;
#pragma unroll
                for (int mt = 0; mt < 2; ++mt) {
                    int r = rA0 + mt * 16;
                    af[cur ^ 1][mt][0] = ctxA[r * 260 + kk + q];
                    af[cur ^ 1][mt][1] = ctxA[(r + 8) * 260 + kk + q];
                    af[cur ^ 1][mt][2] = ctxA[r * 260 + kk + q + 4];
                    af[cur ^ 1][mt][3] = ctxA[(r + 8) * 260 + kk + q + 4];
                }
#pragma unroll
                for (int nt = 0; nt < 2; ++nt) {
                    int cc = cB0 + nt * 8;
                    bf[cur ^ 1][nt][0] = w1b[cc * 260 + kk + q];
                    bf[cur ^ 1][nt][1] = w1b[cc * 260 + kk + q + 4];
                }
            }
#pragma unroll
            for (int mt = 0; mt < 2; ++mt)
#pragma unroll
                for (int nt = 0; nt < 2; ++nt)
                    mma8(c1[mt][nt], af[cur][mt], bf[cur][nt]);
        }

        // epilogue: h = relu(C1 + Ph_i + Pt_j) -> hs (tf32)
#pragma unroll
        for (int mt = 0; mt < 2; ++mt) {
#pragma unroll
            for (int nt = 0; nt < 2; ++nt) {
                int r0 = wm * 32 + mt * 16 + g;
                int r1 = r0 + 8;
                int c0 = wn * 16 + nt * 8 + 2 * q;
                int ii0 = r0 >> 3, jj0 = r0 & 7;
                int ii1 = r1 >> 3, jj1 = r1 & 7;
                float h00 = fmaxf(c1[mt][nt][0] + phs[ii0 * 64 + c0]     + pts[jj0 * 64 + c0],     0.f);
                float h01 = fmaxf(c1[mt][nt][1] + phs[ii0 * 64 + c0 + 1] + pts[jj0 * 64 + c0 + 1], 0.f);
                float h10 = fmaxf(c1[mt][nt][2] + phs[ii1 * 64 + c0]     + pts[jj1 * 64 + c0],     0.f);
                float h11 = fmaxf(c1[mt][nt][3] + phs[ii1 * 64 + c0 + 1] + pts[jj1 * 64 + c0 + 1], 0.f);
                hs[r0 * 68 + c0]     = f2tf(h00);
                hs[r0 * 68 + c0 + 1] = f2tf(h01);
                hs[r1 * 68 + c0]     = f2tf(h10);
                hs[r1 * 68 + c0 + 1] = f2tf(h11);
            }
        }

        cp_wait<0>();          // G2_c landed (w2)
        __syncthreads();       // hs visible; w1/ph/pt free
        stage_w1(fcn); stage_phpt(fcn); cp_commit();   // G1_{c+1} (overlaps GEMM2)

        // ---- GEMM2: K=64, 2-stage fragment pipeline ----
        uint32_t ah[2][2][4], bw[2][8][2];
#pragma unroll
        for (int mt = 0; mt < 2; ++mt) {
            int r = rA0 + mt * 16;
            ah[0][mt][0] = hs[r * 68 + q];
            ah[0][mt][1] = hs[(r + 8) * 68 + q];
            ah[0][mt][2] = hs[r * 68 + q + 4];
            ah[0][mt][3] = hs[(r + 8) * 68 + q + 4];
        }
#pragma unroll
        for (int nt = 0; nt < 8; ++nt) {
            int cc = wn * 64 + nt * 8 + g;
            bw[0][nt][0] = w2s[q * 264 + cc];
            bw[0][nt][1] = w2s[(q + 4) * 264 + cc];
        }

#pragma unroll
        for (int i = 0; i < 8; ++i) {
            int cur = i & 1;
            if (i < 7) {
                int kk = (i + 1) * 8;
#pragma unroll
                for (int mt = 0; mt < 2; ++mt) {
                    int r = rA0 + mt * 16;
                    ah[cur ^ 1][mt][0] = hs[r * 68 + kk + q];
                    ah[cur ^ 1][mt][1] = hs[(r + 8) * 68 + kk + q];
                    ah[cur ^ 1][mt][2] = hs[r * 68 + kk + q + 4];
                    ah[cur ^ 1][mt][3] = hs[(r + 8) * 68 + kk + q + 4];
                }
#pragma unroll
                for (int nt = 0; nt < 8; ++nt) {
                    int cc = wn * 64 + nt * 8 + g;
                    bw[cur ^ 1][nt][0] = w2s[(kk + q) * 264 + cc];
                    bw[cur ^ 1][nt][1] = w2s[(kk + q + 4) * 264 + cc];
                }
            }
#pragma unroll
            for (int nt = 0; nt < 8; ++nt)
#pragma unroll
                for (int mt = 0; mt < 2; ++mt)
                    mma8(oacc[mt][nt], ah[cur][mt], bw[cur][nt]);
        }

        __syncthreads();       // everyone done reading w2s
        stage_w2(fcn); cp_commit();               // G2_{c+1}
    }

    // write output: out[b][i*64+j][h] + b2
    float* outp = out + (size_t)b * (Kk * Kk * Hh);
#pragma unroll
    for (int mt = 0; mt < 2; ++mt) {
#pragma unroll
        for (int nt = 0; nt < 8; ++nt) {
            int r0 = wm * 32 + mt * 16 + g;
            int r1 = r0 + 8;
            int c0 = wn * 64 + nt * 8 + 2 * q;
            int p0 = (I0 + (r0 >> 3)) * 64 + (J0 + (r0 & 7));
            int p1 = (I0 + (r1 >> 3)) * 64 + (J0 + (r1 & 7));
            float2 v0 = make_float2(oacc[mt][nt][0] + b2s[c0], oacc[mt][nt][1] + b2s[c0 + 1]);
            float2 v1 = make_float2(oacc[mt][nt][2] + b2s[c0], oacc[mt][nt][3] + b2s[c0 + 1]);
            *(float2*)&outp[(size_t)p0 * 256 + c0] = v0;
            *(float2*)&outp[(size_t)p1 * 256 + c0] = v1;
        }
    }
}

// ---------------------------------------------------------------------------
extern "C" void kernel_launch(void* const* d_in, const int* in_sizes, int n_in,
                              void* d_out, int out_size) {
    const float* cand = (const float*)d_in[0];
    const float* tok  = (const float*)d_in[1];
    const float* W1   = (const float*)d_in[2];
    const float* b1   = (const float*)d_in[3];
    const float* W2   = (const float*)d_in[4];
    const float* b2   = (const float*)d_in[5];
    const int*   ids  = (const int*)d_in[6];
    float* out = (float*)d_out;

    ctx_kernel<<<Bb * Kk, Hh>>>(tok, ids);
    w1t_kernel<<<dim3(FFN / 32, 256 / 32), dim3(32, 8)>>>(W1);
    w2t_kernel<<<(FFN * Hh) / (256 * 4), 256>>>(W2);
    phpt_kernel<<<dim3(FFN / 64, (Bb * Kk) / 64, 2), 128>>>(cand, W1, b1);

    const int smem_bytes = SMEM_WORDS * 4;  // 223232
    cudaFuncSetAttribute(pair_kernel, cudaFuncAttributeMaxDynamicSharedMemorySize, smem_bytes);
    pair_kernel<<<dim3(8, 8, 8), 256, smem_bytes>>>(b2, out);
}

// round 10
// speedup vs baseline: 2.0486x; 1.8505x over previous
#include <cuda_runtime.h>
#include <cuda_fp16.h>
#include <cstdint>

#define Bb  8
#define Kk  64
#define Ll  1024
#define Hh  256
#define FFN 3072
#define WIN 20
#define F   128
#define NCH (FFN / F)   // 24

// scratch (device globals — no runtime allocation allowed)
__device__ __align__(16) float  g_ctx[Bb * Kk * Hh];    // [B*K, H] window max
__device__ __align__(16) float  g_ph [Bb * Kk * FFN];   // head @ W1a + b1
__device__ __align__(16) float  g_pt [Bb * Kk * FFN];   // tail @ W1b
__device__ __align__(16) __half g_w1h[FFN * Hh];        // W1 ctx block transposed [n=3072][k=256] fp16
__device__ __align__(16) __half g_w2h[Hh * FFN];        // W2 transposed [n=256][k=3072] fp16

__device__ __forceinline__ uint32_t f2tf(float f) {
    uint32_t r;
    asm("cvt.rna.tf32.f32 %0, %1;" : "=r"(r) : "f"(f));
    return r;
}

// tf32 m16n8k8 (used by phpt only)
__device__ __forceinline__ void mma8(float d[4], const uint32_t a[4], const uint32_t b[2]) {
    asm volatile(
        "mma.sync.aligned.m16n8k8.row.col.f32.tf32.tf32.f32 "
        "{%0,%1,%2,%3}, {%4,%5,%6,%7}, {%8,%9}, {%0,%1,%2,%3};"
        : "+f"(d[0]), "+f"(d[1]), "+f"(d[2]), "+f"(d[3])
        : "r"(a[0]), "r"(a[1]), "r"(a[2]), "r"(a[3]), "r"(b[0]), "r"(b[1]));
}

// fp16 m16n8k16 (pair kernel)
__device__ __forceinline__ void mma16(float d[4], const uint32_t a[4], const uint32_t b[2]) {
    asm volatile(
        "mma.sync.aligned.m16n8k16.row.col.f32.f16.f16.f32 "
        "{%0,%1,%2,%3}, {%4,%5,%6,%7}, {%8,%9}, {%0,%1,%2,%3};"
        : "+f"(d[0]), "+f"(d[1]), "+f"(d[2]), "+f"(d[3])
        : "r"(a[0]), "r"(a[1]), "r"(a[2]), "r"(a[3]), "r"(b[0]), "r"(b[1]));
}

__device__ __forceinline__ void cp16(uint32_t dst_smem, const void* src) {
    asm volatile("cp.async.cg.shared.global [%0], [%1], 16;" :: "r"(dst_smem), "l"(src));
}
__device__ __forceinline__ void cp_commit() { asm volatile("cp.async.commit_group;"); }
template <int N> __device__ __forceinline__ void cp_wait() {
    asm volatile("cp.async.wait_group %0;" :: "n"(N));
}

// ---------------------------------------------------------------------------
// Kernel 1: per-span window max over token_reps. grid = B*K, 256 threads.
// ---------------------------------------------------------------------------
__global__ void ctx_kernel(const float* __restrict__ tok,
                           const int* __restrict__ ids) {
    int bk = blockIdx.x;
    int b  = bk >> 6;
    int h  = threadIdx.x;
    int s  = ids[bk * 2 + 0];
    int e  = ids[bk * 2 + 1];

    float m = __int_as_float(0xff800000);

    int lo = s - WIN; if (lo < 0) lo = 0;
    for (int p = lo; p < s; ++p)
        m = fmaxf(m, tok[((size_t)b * Ll + p) * Hh + h]);

    int hi = e + WIN; if (hi > Ll - 1) hi = Ll - 1;
    for (int p = e + 1; p <= hi; ++p)
        m = fmaxf(m, tok[((size_t)b * Ll + p) * Hh + h]);

    g_ctx[(size_t)bk * Hh + h] = m;
}

// ---------------------------------------------------------------------------
// Prep A: transpose+convert W1 ctx block -> g_w1h[n][k] fp16. grid (96,8), blk (32,8)
// ---------------------------------------------------------------------------
__global__ void w1t_kernel(const float* __restrict__ W1) {
    __shared__ float tile[32][33];
    int n0 = blockIdx.x * 32, k0 = blockIdx.y * 32;
    int tx = threadIdx.x, ty = threadIdx.y;
#pragma unroll
    for (int r = 0; r < 4; ++r) {
        int k = ty + r * 8;
        tile[tx][k] = W1[(size_t)(512 + k0 + k) * FFN + n0 + tx];
    }
    __syncthreads();
#pragma unroll
    for (int r = 0; r < 4; ++r) {
        int n = ty + r * 8;
        g_w1h[(size_t)(n0 + n) * 256 + k0 + tx] = __float2half_rn(tile[n][tx]);
    }
}

// Prep B: transpose+convert W2 -> g_w2h[n=256][k=3072] fp16. grid (8,96), blk (32,8)
__global__ void w2t_kernel(const float* __restrict__ W2) {
    __shared__ float tile[32][33];
    int n0 = blockIdx.x * 32, k0 = blockIdx.y * 32;
    int tx = threadIdx.x, ty = threadIdx.y;
#pragma unroll
    for (int r = 0; r < 4; ++r) {
        int k = ty + r * 8;
        tile[tx][k] = W2[(size_t)(k0 + k) * Hh + n0 + tx];
    }
    __syncthreads();
#pragma unroll
    for (int r = 0; r < 4; ++r) {
        int n = ty + r * 8;
        g_w2h[(size_t)(n0 + n) * FFN + k0 + tx] = __float2half_rn(tile[n][tx]);
    }
}

// ---------------------------------------------------------------------------
// Kernel 2: Ph = cand @ W1[0:256] + b1 ; Pt = cand @ W1[256:512]  (tf32 mma)
// ---------------------------------------------------------------------------
__global__ __launch_bounds__(128) void phpt_kernel(const float* __restrict__ cand,
                                                   const float* __restrict__ W1,
                                                   const float* __restrict__ b1) {
    __shared__ uint32_t a_s[64 * 68];
    __shared__ uint32_t b_s[64 * 68];

    int tid = threadIdx.x;
    int w = tid >> 5, lane = tid & 31;
    int g = lane >> 2, q = lane & 3;
    int wm = w >> 1, wn = w & 1;
    int n0 = blockIdx.x * 64;
    int m0 = blockIdx.y * 64;
    int s  = blockIdx.z;

    float acc[2][4][4];
#pragma unroll
    for (int mt = 0; mt < 2; ++mt)
#pragma unroll
        for (int nt = 0; nt < 4; ++nt)
#pragma unroll
            for (int r = 0; r < 4; ++r) acc[mt][nt][r] = 0.f;

    for (int kc = 0; kc < 256; kc += 64) {
        __syncthreads();
#pragma unroll
        for (int it = 0; it < 8; ++it) {
            int idx = it * 128 + tid;
            int m = idx >> 4, c4 = (idx & 15) << 2;
            float4 v = *(const float4*)&cand[(size_t)(m0 + m) * 256 + kc + c4];
            uint32_t* dst = &a_s[m * 68 + c4];
            dst[0] = f2tf(v.x); dst[1] = f2tf(v.y); dst[2] = f2tf(v.z); dst[3] = f2tf(v.w);
        }
#pragma unroll
        for (int it = 0; it < 8; ++it) {
            int idx = it * 128 + tid;
            int kk = idx >> 4, n4 = (idx & 15) << 2;
            float4 v = *(const float4*)&W1[(size_t)(s * 256 + kc + kk) * FFN + n0 + n4];
            b_s[(n4 + 0) * 68 + kk] = f2tf(v.x);
            b_s[(n4 + 1) * 68 + kk] = f2tf(v.y);
            b_s[(n4 + 2) * 68 + kk] = f2tf(v.z);
            b_s[(n4 + 3) * 68 + kk] = f2tf(v.w);
        }
        __syncthreads();

#pragma unroll
        for (int ks = 0; ks < 64; ks += 8) {
            uint32_t a[2][4], bb[4][2];
#pragma unroll
            for (int mt = 0; mt < 2; ++mt) {
                int r = wm * 32 + mt * 16 + g;
                a[mt][0] = a_s[r * 68 + ks + q];
                a[mt][1] = a_s[(r + 8) * 68 + ks + q];
                a[mt][2] = a_s[r * 68 + ks + q + 4];
                a[mt][3] = a_s[(r + 8) * 68 + ks + q + 4];
            }
#pragma unroll
            for (int nt = 0; nt < 4; ++nt) {
                int c = wn * 32 + nt * 8 + g;
                bb[nt][0] = b_s[c * 68 + ks + q];
                bb[nt][1] = b_s[c * 68 + ks + q + 4];
            }
#pragma unroll
            for (int mt = 0; mt < 2; ++mt)
#pragma unroll
                for (int nt = 0; nt < 4; ++nt)
                    mma8(acc[mt][nt], a[mt], bb[nt]);
        }
    }

    float* out = s ? g_pt : g_ph;
#pragma unroll
    for (int mt = 0; mt < 2; ++mt) {
#pragma unroll
        for (int nt = 0; nt < 4; ++nt) {
            int r0 = m0 + wm * 32 + mt * 16 + g;
            int c0 = n0 + wn * 32 + nt * 8 + 2 * q;
            float bias0 = s ? 0.f : b1[c0];
            float bias1 = s ? 0.f : b1[c0 + 1];
            float2 v0 = make_float2(acc[mt][nt][0] + bias0, acc[mt][nt][1] + bias1);
            float2 v1 = make_float2(acc[mt][nt][2] + bias0, acc[mt][nt][3] + bias1);
            *(float2*)&out[(size_t)r0 * FFN + c0] = v0;
            *(float2*)&out[(size_t)(r0 + 8) * FFN + c0] = v1;
        }
    }
}

// ---------------------------------------------------------------------------
// Kernel 3: fp16 fused pairwise kernel. 256 threads / 8 warps (2m x 4n), F=128.
// Per chunk: GEMM1 h=64x128 from ctxA[64x256]@W1 (m16n8k16), epi -> hs (fp16),
//            GEMM2 out[64x256] += hs @ W2 (k=128).
// SMEM (words): k-row strides 132 (256 halves + pad) / 68 (128 halves + pad),
// both ≡ 4 mod 32 -> conflict-free fragment access (banks 4g+q).
//   ctxA 64x132  @0      (8448)
//   w1b  128x132 @8448   (16896)
//   w2s  256x68  @25344  (17408)
//   hs   64x68   @42752  (4352)
//   phs  8x128 f32 @47104 | pts @48128 | b2s @49152  -> 49408 words (197632 B)
// ---------------------------------------------------------------------------
#define CTXA_W 0
#define W1B_W  8448
#define W2S_W  25344
#define HS_W   42752
#define PHS_W  47104
#define PTS_W  48128
#define B2S_W  49152
#define SMEM_WORDS 49408

__global__ __launch_bounds__(256, 1) void pair_kernel(const float* __restrict__ b2,
                                                      float* __restrict__ out) {
    extern __shared__ __align__(16) uint32_t sm[];
    uint32_t* ctxA = sm + CTXA_W;   // fp16 [64][264 halves] as words
    uint32_t* w1b  = sm + W1B_W;    // fp16 [128][264 halves]
    uint32_t* w2s  = sm + W2S_W;    // fp16 [256][136 halves]
    uint32_t* hs   = sm + HS_W;     // fp16 [64][136 halves]
    float*    phs  = (float*)(sm + PHS_W);
    float*    pts  = (float*)(sm + PTS_W);
    float*    b2s  = (float*)(sm + B2S_W);

    const uint32_t w1b_u = (uint32_t)__cvta_generic_to_shared(w1b);
    const uint32_t w2s_u = (uint32_t)__cvta_generic_to_shared(w2s);
    const uint32_t phs_u = (uint32_t)__cvta_generic_to_shared(phs);
    const uint32_t pts_u = (uint32_t)__cvta_generic_to_shared(pts);

    int tid = threadIdx.x;
    int w = tid >> 5, lane = tid & 31;
    int g = lane >> 2, q = lane & 3;
    int wm = w >> 2;    // 0..1
    int wn = w & 3;     // 0..3
    int b  = blockIdx.z;
    int I0 = blockIdx.y * 8;
    int J0 = blockIdx.x * 8;

    const float* phbase = g_ph + (size_t)(b * Kk + I0) * FFN;
    const float* ptbase = g_pt + (size_t)(b * Kk + J0) * FFN;

    // --- staging helpers (16B cp.async, fp16 payloads) ---
    auto stage_w1 = [&](int fc) {              // [128 n][256 k halves], stride 132 words
#pragma unroll
        for (int i = 0; i < 16; ++i) {
            int idx = i * 256 + tid;           // 4096 x 16B
            int n = idx >> 5, k8 = (idx & 31) << 3;   // 8 halves per cp
            cp16(w1b_u + (uint32_t)(n * 132 + (k8 >> 1)) * 4,
                 g_w1h + (size_t)(fc + n) * 256 + k8);
        }
    };
    auto stage_w2 = [&](int fc) {              // [256 n][128 k halves], stride 68 words
#pragma unroll
        for (int i = 0; i < 16; ++i) {
            int idx = i * 256 + tid;           // 4096 x 16B
            int n = idx >> 4, k8 = (idx & 15) << 3;
            cp16(w2s_u + (uint32_t)(n * 68 + (k8 >> 1)) * 4,
                 g_w2h + (size_t)n * FFN + fc + k8);
        }
    };
    auto stage_phpt = [&](int fc) {            // ph/pt [8][128] fp32
        int row = tid >> 5, c4 = (tid & 31) << 2;
        cp16(phs_u + (uint32_t)(row * 128 + c4) * 4, phbase + (size_t)row * FFN + fc + c4);
        cp16(pts_u + (uint32_t)(row * 128 + c4) * 4, ptbase + (size_t)row * FFN + fc + c4);
    };

    b2s[tid] = b2[tid];

    // prefetch chunk 0: G1 = {w1, ph/pt}, G2 = {w2}
    stage_w1(0); stage_phpt(0); cp_commit();
    stage_w2(0);                cp_commit();

    // build ctxA[r][k] fp16 = max(ctx_i, ctx_j), r = ii*8 + jj, stride 132 words
    const float* ctxb = g_ctx + (size_t)b * Kk * Hh;
    for (int idx = tid; idx < 64 * 64; idx += 256) {
        int r = idx >> 6, k4 = (idx & 63) << 2;
        float4 va = *(const float4*)&ctxb[(I0 + (r >> 3)) * 256 + k4];
        float4 vb = *(const float4*)&ctxb[(J0 + (r & 7)) * 256 + k4];
        __half2 h0 = __floats2half2_rn(fmaxf(va.x, vb.x), fmaxf(va.y, vb.y));
        __half2 h1 = __floats2half2_rn(fmaxf(va.z, vb.z), fmaxf(va.w, vb.w));
        uint32_t* dst = &ctxA[r * 132 + (k4 >> 1)];
        dst[0] = *(uint32_t*)&h0;
        dst[1] = *(uint32_t*)&h1;
    }

    float oacc[2][8][4];
#pragma unroll
    for (int mt = 0; mt < 2; ++mt)
#pragma unroll
        for (int nt = 0; nt < 8; ++nt)
#pragma unroll
            for (int r = 0; r < 4; ++r) oacc[mt][nt][r] = 0.f;

    const int rA0 = wm * 32 + g;

    for (int c = 0; c < NCH; ++c) {
        int fc  = c * F;
        int fcn = (c < NCH - 1) ? fc + F : 0;

        cp_wait<1>();          // G1_c landed (w1 + ph/pt)
        __syncthreads();       // + ctxA/hs hazards

        // ---- GEMM1: [64 x 128] = ctxA[64x256] @ w1^T, k16 x 16 iters ----
        float c1[2][4][4];
#pragma unroll
        for (int mt = 0; mt < 2; ++mt)
#pragma unroll
            for (int nt = 0; nt < 4; ++nt)
#pragma unroll
                for (int r = 0; r < 4; ++r) c1[mt][nt][r] = 0.f;

#pragma unroll
        for (int i = 0; i < 16; ++i) {
            int kb = i * 8;    // word offset of this k16 slab
            uint32_t a[2][4], bb[4][2];
#pragma unroll
            for (int mt = 0; mt < 2; ++mt) {
                int r = rA0 + mt * 16;
                a[mt][0] = ctxA[r * 132 + kb + q];
                a[mt][1] = ctxA[(r + 8) * 132 + kb + q];
                a[mt][2] = ctxA[r * 132 + kb + q + 4];
                a[mt][3] = ctxA[(r + 8) * 132 + kb + q + 4];
            }
#pragma unroll
            for (int nt = 0; nt < 4; ++nt) {
                int cc = wn * 32 + nt * 8 + g;
                bb[nt][0] = w1b[cc * 132 + kb + q];
                bb[nt][1] = w1b[cc * 132 + kb + q + 4];
            }
#pragma unroll
            for (int mt = 0; mt < 2; ++mt)
#pragma unroll
                for (int nt = 0; nt < 4; ++nt)
                    mma16(c1[mt][nt], a[mt], bb[nt]);
        }

        // epilogue: h = relu(C1 + Ph_i + Pt_j) -> hs fp16 (stride 68 words)
#pragma unroll
        for (int mt = 0; mt < 2; ++mt) {
#pragma unroll
            for (int nt = 0; nt < 4; ++nt) {
                int r0 = wm * 32 + mt * 16 + g;
                int r1 = r0 + 8;
                int c0 = wn * 32 + nt * 8 + 2 * q;   // col within [0,128)
                int ii0 = r0 >> 3, jj0 = r0 & 7;
                int ii1 = r1 >> 3, jj1 = r1 & 7;
                float h00 = fmaxf(c1[mt][nt][0] + phs[ii0 * 128 + c0]     + pts[jj0 * 128 + c0],     0.f);
                float h01 = fmaxf(c1[mt][nt][1] + phs[ii0 * 128 + c0 + 1] + pts[jj0 * 128 + c0 + 1], 0.f);
                float h10 = fmaxf(c1[mt][nt][2] + phs[ii1 * 128 + c0]     + pts[jj1 * 128 + c0],     0.f);
                float h11 = fmaxf(c1[mt][nt][3] + phs[ii1 * 128 + c0 + 1] + pts[jj1 * 128 + c0 + 1], 0.f);
                __half2 p0 = __floats2half2_rn(h00, h01);
                __half2 p1 = __floats2half2_rn(h10, h11);
                hs[r0 * 68 + (c0 >> 1)] = *(uint32_t*)&p0;
                hs[r1 * 68 + (c0 >> 1)] = *(uint32_t*)&p1;
            }
        }

        cp_wait<0>();          // G2_c landed (w2)
        __syncthreads();       // hs visible; w1/ph/pt free
        stage_w1(fcn); stage_phpt(fcn); cp_commit();   // G1_{c+1} (overlaps GEMM2)

        // ---- GEMM2: out[64x256] += hs[64x128] @ w2^T, k16 x 8 iters ----
#pragma unroll
        for (int i = 0; i < 8; ++i) {
            int kb = i * 8;
            uint32_t a[2][4];
#pragma unroll
            for (int mt = 0; mt < 2; ++mt) {
                int r = rA0 + mt * 16;
                a[mt][0] = hs[r * 68 + kb + q];
                a[mt][1] = hs[(r + 8) * 68 + kb + q];
                a[mt][2] = hs[r * 68 + kb + q + 4];
                a[mt][3] = hs[(r + 8) * 68 + kb + q + 4];
            }
#pragma unroll
            for (int nt = 0; nt < 8; ++nt) {
                int cc = wn * 64 + nt * 8 + g;
                uint32_t bb[2];
                bb[0] = w2s[cc * 68 + kb + q];
                bb[1] = w2s[cc * 68 + kb + q + 4];
#pragma unroll
                for (int mt = 0; mt < 2; ++mt)
                    mma16(oacc[mt][nt], a[mt], bb);
            }
        }

        __syncthreads();       // everyone done reading w2s (+ hs before next epi)
        stage_w2(fcn); cp_commit();               // G2_{c+1}
    }

    // write output: out[b][i*64+j][h] + b2
    float* outp = out + (size_t)b * (Kk * Kk * Hh);
#pragma unroll
    for (int mt = 0; mt < 2; ++mt) {
#pragma unroll
        for (int nt = 0; nt < 8; ++nt) {
            int r0 = wm * 32 + mt * 16 + g;
            int r1 = r0 + 8;
            int c0 = wn * 64 + nt * 8 + 2 * q;
            int p0 = (I0 + (r0 >> 3)) * 64 + (J0 + (r0 & 7));
            int p1 = (I0 + (r1 >> 3)) * 64 + (J0 + (r1 & 7));
            float2 v0 = make_float2(oacc[mt][nt][0] + b2s[c0], oacc[mt][nt][1] + b2s[c0 + 1]);
            float2 v1 = make_float2(oacc[mt][nt][2] + b2s[c0], oacc[mt][nt][3] + b2s[c0 + 1]);
            *(float2*)&outp[(size_t)p0 * 256 + c0] = v0;
            *(float2*)&outp[(size_t)p1 * 256 + c0] = v1;
        }
    }
}

// ---------------------------------------------------------------------------
extern "C" void kernel_launch(void* const* d_in, const int* in_sizes, int n_in,
                              void* d_out, int out_size) {
    const float* cand = (const float*)d_in[0];
    const float* tok  = (const float*)d_in[1];
    const float* W1   = (const float*)d_in[2];
    const float* b1   = (const float*)d_in[3];
    const float* W2   = (const float*)d_in[4];
    const float* b2   = (const float*)d_in[5];
    const int*   ids  = (const int*)d_in[6];
    float* out = (float*)d_out;

    ctx_kernel<<<Bb * Kk, Hh>>>(tok, ids);
    w1t_kernel<<<dim3(FFN / 32, 256 / 32), dim3(32, 8)>>>(W1);
    w2t_kernel<<<dim3(Hh / 32, FFN / 32), dim3(32, 8)>>>(W2);
    phpt_kernel<<<dim3(FFN / 64, (Bb * Kk) / 64, 2), 128>>>(cand, W1, b1);

    const int smem_bytes = SMEM_WORDS * 4;  // 197632
    cudaFuncSetAttribute(pair_kernel, cudaFuncAttributeMaxDynamicSharedMemorySize, smem_bytes);
    pair_kernel<<<dim3(8, 8, 8), 256, smem_bytes>>>(b2, out);
}

// round 11
// speedup vs baseline: 2.0649x; 1.0080x over previous
#include <cuda_runtime.h>
#include <cuda_fp16.h>
#include <cstdint>

#define Bb  8
#define Kk  64
#define Ll  1024
#define Hh  256
#define FFN 3072
#define WIN 20
#define F   64
#define NCH (FFN / F)   // 48

// scratch (device globals — no runtime allocation allowed)
__device__ __align__(16) float  g_ctx[Bb * Kk * Hh];    // [B*K, H] window max
__device__ __align__(16) float  g_ph [Bb * Kk * FFN];   // head @ W1a + b1
__device__ __align__(16) float  g_pt [Bb * Kk * FFN];   // tail @ W1b
__device__ __align__(16) __half g_w1h[FFN * Hh];        // W1 ctx block transposed [n=3072][k=256] fp16
__device__ __align__(16) __half g_w2h[Hh * FFN];        // W2 transposed [n=256][k=3072] fp16

// fp16 m16n8k16
__device__ __forceinline__ void mma16(float d[4], const uint32_t a[4], const uint32_t b[2]) {
    asm volatile(
        "mma.sync.aligned.m16n8k16.row.col.f32.f16.f16.f32 "
        "{%0,%1,%2,%3}, {%4,%5,%6,%7}, {%8,%9}, {%0,%1,%2,%3};"
        : "+f"(d[0]), "+f"(d[1]), "+f"(d[2]), "+f"(d[3])
        : "r"(a[0]), "r"(a[1]), "r"(a[2]), "r"(a[3]), "r"(b[0]), "r"(b[1]));
}

__device__ __forceinline__ void cp16(uint32_t dst_smem, const void* src) {
    asm volatile("cp.async.cg.shared.global [%0], [%1], 16;" :: "r"(dst_smem), "l"(src));
}
__device__ __forceinline__ void cp_commit() { asm volatile("cp.async.commit_group;"); }
template <int N> __device__ __forceinline__ void cp_wait() {
    asm volatile("cp.async.wait_group %0;" :: "n"(N));
}

// ---------------------------------------------------------------------------
// Kernel 1: per-span window max over token_reps. grid = B*K, 256 threads.
// ---------------------------------------------------------------------------
__global__ void ctx_kernel(const float* __restrict__ tok,
                           const int* __restrict__ ids) {
    int bk = blockIdx.x;
    int b  = bk >> 6;
    int h  = threadIdx.x;
    int s  = ids[bk * 2 + 0];
    int e  = ids[bk * 2 + 1];

    float m = __int_as_float(0xff800000);

    int lo = s - WIN; if (lo < 0) lo = 0;
    for (int p = lo; p < s; ++p)
        m = fmaxf(m, tok[((size_t)b * Ll + p) * Hh + h]);

    int hi = e + WIN; if (hi > Ll - 1) hi = Ll - 1;
    for (int p = e + 1; p <= hi; ++p)
        m = fmaxf(m, tok[((size_t)b * Ll + p) * Hh + h]);

    g_ctx[(size_t)bk * Hh + h] = m;
}

// ---------------------------------------------------------------------------
// Prep A: transpose+convert W1 ctx block -> g_w1h[n][k] fp16. grid (96,8), blk (32,8)
// ---------------------------------------------------------------------------
__global__ void w1t_kernel(const float* __restrict__ W1) {
    __shared__ float tile[32][33];
    int n0 = blockIdx.x * 32, k0 = blockIdx.y * 32;
    int tx = threadIdx.x, ty = threadIdx.y;
#pragma unroll
    for (int r = 0; r < 4; ++r) {
        int k = ty + r * 8;
        tile[tx][k] = W1[(size_t)(512 + k0 + k) * FFN + n0 + tx];
    }
    __syncthreads();
#pragma unroll
    for (int r = 0; r < 4; ++r) {
        int n = ty + r * 8;
        g_w1h[(size_t)(n0 + n) * 256 + k0 + tx] = __float2half_rn(tile[n][tx]);
    }
}

// Prep B: transpose+convert W2 -> g_w2h[n=256][k=3072] fp16. grid (8,96), blk (32,8)
__global__ void w2t_kernel(const float* __restrict__ W2) {
    __shared__ float tile[32][33];
    int n0 = blockIdx.x * 32, k0 = blockIdx.y * 32;
    int tx = threadIdx.x, ty = threadIdx.y;
#pragma unroll
    for (int r = 0; r < 4; ++r) {
        int k = ty + r * 8;
        tile[tx][k] = W2[(size_t)(k0 + k) * Hh + n0 + tx];
    }
    __syncthreads();
#pragma unroll
    for (int r = 0; r < 4; ++r) {
        int n = ty + r * 8;
        g_w2h[(size_t)(n0 + n) * FFN + k0 + tx] = __float2half_rn(tile[n][tx]);
    }
}

// ---------------------------------------------------------------------------
// Kernel 2: Ph = cand @ W1[0:256] + b1 ; Pt = cand @ W1[256:512]  (fp16 mma)
// M=512, N=3072, K=256. grid (48, 8, 2), 128 threads (2m x 2n warps).
// ---------------------------------------------------------------------------
__global__ __launch_bounds__(128) void phpt_kernel(const float* __restrict__ cand,
                                                   const float* __restrict__ W1,
                                                   const float* __restrict__ b1) {
    __shared__ uint32_t a_s[64 * 36];   // fp16 [64 m][64 k halves + pad]
    __shared__ uint32_t b_s[64 * 36];   // fp16 [64 n][64 k halves + pad]

    int tid = threadIdx.x;
    int w = tid >> 5, lane = tid & 31;
    int g = lane >> 2, q = lane & 3;
    int wm = w >> 1, wn = w & 1;
    int n0 = blockIdx.x * 64;
    int m0 = blockIdx.y * 64;
    int s  = blockIdx.z;

    float acc[2][4][4];
#pragma unroll
    for (int mt = 0; mt < 2; ++mt)
#pragma unroll
        for (int nt = 0; nt < 4; ++nt)
#pragma unroll
            for (int r = 0; r < 4; ++r) acc[mt][nt][r] = 0.f;

    for (int kc = 0; kc < 256; kc += 64) {
        __syncthreads();
        // stage A [64 m][64 k] as half2 words (word w = halves kc+2w, kc+2w+1)
#pragma unroll
        for (int it = 0; it < 16; ++it) {
            int idx = it * 128 + tid;              // 2048 words
            int m = idx >> 5, ww = idx & 31;
            float2 v = *(const float2*)&cand[(size_t)(m0 + m) * 256 + kc + 2 * ww];
            __half2 h = __floats2half2_rn(v.x, v.y);
            a_s[m * 36 + ww] = *(uint32_t*)&h;
        }
        // stage B transposed: word w of col n = (W1[kc+2w][n], W1[kc+2w+1][n])
#pragma unroll
        for (int it = 0; it < 16; ++it) {
            int idx = it * 128 + tid;
            int n = idx & 63, ww = idx >> 6;
            float v0 = W1[(size_t)(s * 256 + kc + 2 * ww) * FFN + n0 + n];
            float v1 = W1[(size_t)(s * 256 + kc + 2 * ww + 1) * FFN + n0 + n];
            __half2 h = __floats2half2_rn(v0, v1);
            b_s[n * 36 + ww] = *(uint32_t*)&h;
        }
        __syncthreads();

#pragma unroll
        for (int ks = 0; ks < 32; ks += 8) {       // 4 k16 steps
            uint32_t a[2][4], bb[4][2];
#pragma unroll
            for (int mt = 0; mt < 2; ++mt) {
                int r = wm * 32 + mt * 16 + g;
                a[mt][0] = a_s[r * 36 + ks + q];
                a[mt][1] = a_s[(r + 8) * 36 + ks + q];
                a[mt][2] = a_s[r * 36 + ks + q + 4];
                a[mt][3] = a_s[(r + 8) * 36 + ks + q + 4];
            }
#pragma unroll
            for (int nt = 0; nt < 4; ++nt) {
                int c = wn * 32 + nt * 8 + g;
                bb[nt][0] = b_s[c * 36 + ks + q];
                bb[nt][1] = b_s[c * 36 + ks + q + 4];
            }
#pragma unroll
            for (int mt = 0; mt < 2; ++mt)
#pragma unroll
                for (int nt = 0; nt < 4; ++nt)
                    mma16(acc[mt][nt], a[mt], bb[nt]);
        }
    }

    float* out = s ? g_pt : g_ph;
#pragma unroll
    for (int mt = 0; mt < 2; ++mt) {
#pragma unroll
        for (int nt = 0; nt < 4; ++nt) {
            int r0 = m0 + wm * 32 + mt * 16 + g;
            int c0 = n0 + wn * 32 + nt * 8 + 2 * q;
            float bias0 = s ? 0.f : b1[c0];
            float bias1 = s ? 0.f : b1[c0 + 1];
            float2 v0 = make_float2(acc[mt][nt][0] + bias0, acc[mt][nt][1] + bias1);
            float2 v1 = make_float2(acc[mt][nt][2] + bias0, acc[mt][nt][3] + bias1);
            *(float2*)&out[(size_t)r0 * FFN + c0] = v0;
            *(float2*)&out[(size_t)(r0 + 8) * FFN + c0] = v1;
        }
    }
}

// ---------------------------------------------------------------------------
// Kernel 3: fp16 fused pairwise kernel. 256 threads / 8 warps (2m x 4n), F=64,
// slim SMEM for 2 CTAs/SM. ph/pt/b2 via __ldg (L2-resident).
// SMEM (words): ctxA 64x132 @0 | w1b 64x132 @8448 | w2s 256x36 @16896
//               | hs 64x36 @26112  -> 28416 words = 113664 B per CTA.
// ---------------------------------------------------------------------------
#define CTXA_W 0
#define W1B_W  8448
#define W2S_W  16896
#define HS_W   26112
#define SMEM_WORDS 28416

__global__ __launch_bounds__(256, 2) void pair_kernel(const float* __restrict__ b2,
                                                      float* __restrict__ out) {
    extern __shared__ __align__(16) uint32_t sm[];
    uint32_t* ctxA = sm + CTXA_W;   // fp16 [64][264 halves] as words (stride 132)
    uint32_t* w1b  = sm + W1B_W;    // fp16 [64 n][264 halves]
    uint32_t* w2s  = sm + W2S_W;    // fp16 [256 n][72 halves] (stride 36)
    uint32_t* hs   = sm + HS_W;     // fp16 [64][72 halves]

    const uint32_t w1b_u = (uint32_t)__cvta_generic_to_shared(w1b);
    const uint32_t w2s_u = (uint32_t)__cvta_generic_to_shared(w2s);

    int tid = threadIdx.x;
    int w = tid >> 5, lane = tid & 31;
    int g = lane >> 2, q = lane & 3;
    int wm = w >> 2;    // 0..1
    int wn = w & 3;     // 0..3
    int b  = blockIdx.z;
    int I0 = blockIdx.y * 8;
    int J0 = blockIdx.x * 8;

    const float* phbase = g_ph + (size_t)(b * Kk + I0) * FFN;
    const float* ptbase = g_pt + (size_t)(b * Kk + J0) * FFN;

    // --- staging helpers (16B cp.async, fp16 payloads) ---
    auto stage_w1 = [&](int fc) {              // [64 n][256 k halves], stride 132 words
#pragma unroll
        for (int i = 0; i < 8; ++i) {
            int idx = i * 256 + tid;           // 2048 x 16B
            int n = idx >> 5, k8 = (idx & 31) << 3;
            cp16(w1b_u + (uint32_t)(n * 132 + (k8 >> 1)) * 4,
                 g_w1h + (size_t)(fc + n) * 256 + k8);
        }
    };
    auto stage_w2 = [&](int fc) {              // [256 n][64 k halves], stride 36 words
#pragma unroll
        for (int i = 0; i < 8; ++i) {
            int idx = i * 256 + tid;           // 2048 x 16B
            int n = idx >> 3, k8 = (idx & 7) << 3;
            cp16(w2s_u + (uint32_t)(n * 36 + (k8 >> 1)) * 4,
                 g_w2h + (size_t)n * FFN + fc + k8);
        }
    };

    // prefetch chunk 0: G1 = {w1}, G2 = {w2}
    stage_w1(0); cp_commit();
    stage_w2(0); cp_commit();

    // build ctxA[r][k] fp16 = max(ctx_i, ctx_j), r = ii*8 + jj, stride 132 words
    const float* ctxb = g_ctx + (size_t)b * Kk * Hh;
    for (int idx = tid; idx < 64 * 64; idx += 256) {
        int r = idx >> 6, k4 = (idx & 63) << 2;
        float4 va = *(const float4*)&ctxb[(I0 + (r >> 3)) * 256 + k4];
        float4 vb = *(const float4*)&ctxb[(J0 + (r & 7)) * 256 + k4];
        __half2 h0 = __floats2half2_rn(fmaxf(va.x, vb.x), fmaxf(va.y, vb.y));
        __half2 h1 = __floats2half2_rn(fmaxf(va.z, vb.z), fmaxf(va.w, vb.w));
        uint32_t* dst = &ctxA[r * 132 + (k4 >> 1)];
        dst[0] = *(uint32_t*)&h0;
        dst[1] = *(uint32_t*)&h1;
    }

    float oacc[2][8][4];
#pragma unroll
    for (int mt = 0; mt < 2; ++mt)
#pragma unroll
        for (int nt = 0; nt < 8; ++nt)
#pragma unroll
            for (int r = 0; r < 4; ++r) oacc[mt][nt][r] = 0.f;

    const int rA0 = wm * 32 + g;
    const int jj  = g;                      // (rA0)&7 == (rA0+8)&7 etc. per mt below

    for (int c = 0; c < NCH; ++c) {
        int fc  = c * F;
        int fcn = (c < NCH - 1) ? fc + F : 0;

        cp_wait<1>();          // G1_c landed (w1)
        __syncthreads();       // + ctxA/hs hazards

        // prefetch ph/pt for this chunk's epilogue (L2-resident, covered by GEMM1)
        float2 phv[2][2][2], ptv[2];
#pragma unroll
        for (int mt = 0; mt < 2; ++mt) {
            int ii = 4 * wm + 2 * mt;
#pragma unroll
            for (int nt = 0; nt < 2; ++nt) {
                int col = fc + wn * 16 + nt * 8 + 2 * q;
                phv[mt][0][nt] = __ldg((const float2*)&phbase[(size_t)ii * FFN + col]);
                phv[mt][1][nt] = __ldg((const float2*)&phbase[(size_t)(ii + 1) * FFN + col]);
            }
        }
#pragma unroll
        for (int nt = 0; nt < 2; ++nt)
            ptv[nt] = __ldg((const float2*)&ptbase[(size_t)jj * FFN + fc + wn * 16 + nt * 8 + 2 * q]);

        // ---- GEMM1: [64 x 64] = ctxA[64x256] @ w1^T, 16 k16-steps ----
        float c1[2][2][4];
#pragma unroll
        for (int mt = 0; mt < 2; ++mt)
#pragma unroll
            for (int nt = 0; nt < 2; ++nt)
#pragma unroll
                for (int r = 0; r < 4; ++r) c1[mt][nt][r] = 0.f;

#pragma unroll
        for (int i = 0; i < 16; ++i) {
            int kb = i * 8;
            uint32_t a[2][4], bb[2][2];
#pragma unroll
            for (int mt = 0; mt < 2; ++mt) {
                int r = rA0 + mt * 16;
                a[mt][0] = ctxA[r * 132 + kb + q];
                a[mt][1] = ctxA[(r + 8) * 132 + kb + q];
                a[mt][2] = ctxA[r * 132 + kb + q + 4];
                a[mt][3] = ctxA[(r + 8) * 132 + kb + q + 4];
            }
#pragma unroll
            for (int nt = 0; nt < 2; ++nt) {
                int cc = wn * 16 + nt * 8 + g;
                bb[nt][0] = w1b[cc * 132 + kb + q];
                bb[nt][1] = w1b[cc * 132 + kb + q + 4];
            }
#pragma unroll
            for (int mt = 0; mt < 2; ++mt)
#pragma unroll
                for (int nt = 0; nt < 2; ++nt)
                    mma16(c1[mt][nt], a[mt], bb[nt]);
        }

        // epilogue: h = relu(C1 + Ph_i + Pt_j) -> hs fp16 (stride 36 words)
#pragma unroll
        for (int mt = 0; mt < 2; ++mt) {
#pragma unroll
            for (int nt = 0; nt < 2; ++nt) {
                int r0 = wm * 32 + mt * 16 + g;
                int r1 = r0 + 8;
                int c0 = wn * 16 + nt * 8 + 2 * q;   // col within [0,64)
                float2 ph0 = phv[mt][0][nt];
                float2 ph1 = phv[mt][1][nt];
                float2 pt  = ptv[nt];
                float h00 = fmaxf(c1[mt][nt][0] + ph0.x + pt.x, 0.f);
                float h01 = fmaxf(c1[mt][nt][1] + ph0.y + pt.y, 0.f);
                float h10 = fmaxf(c1[mt][nt][2] + ph1.x + pt.x, 0.f);
                float h11 = fmaxf(c1[mt][nt][3] + ph1.y + pt.y, 0.f);
                __half2 p0 = __floats2half2_rn(h00, h01);
                __half2 p1 = __floats2half2_rn(h10, h11);
                hs[r0 * 36 + (c0 >> 1)] = *(uint32_t*)&p0;
                hs[r1 * 36 + (c0 >> 1)] = *(uint32_t*)&p1;
            }
        }

        cp_wait<0>();          // G2_c landed (w2)
        __syncthreads();       // hs visible; w1 free
        stage_w1(fcn); cp_commit();   // G1_{c+1} (overlaps GEMM2)

        // ---- GEMM2: out[64x256] += hs[64x64] @ w2^T, 4 k16-steps ----
#pragma unroll
        for (int i = 0; i < 4; ++i) {
            int kb = i * 8;
            uint32_t a[2][4];
#pragma unroll
            for (int mt = 0; mt < 2; ++mt) {
                int r = rA0 + mt * 16;
                a[mt][0] = hs[r * 36 + kb + q];
                a[mt][1] = hs[(r + 8) * 36 + kb + q];
                a[mt][2] = hs[r * 36 + kb + q + 4];
                a[mt][3] = hs[(r + 8) * 36 + kb + q + 4];
            }
#pragma unroll
            for (int nt = 0; nt < 8; ++nt) {
                int cc = wn * 64 + nt * 8 + g;
                uint32_t bb[2];
                bb[0] = w2s[cc * 36 + kb + q];
                bb[1] = w2s[cc * 36 + kb + q + 4];
#pragma unroll
                for (int mt = 0; mt < 2; ++mt)
                    mma16(oacc[mt][nt], a[mt], bb);
            }
        }

        __syncthreads();       // everyone done reading w2s + hs
        stage_w2(fcn); cp_commit();   // G2_{c+1}
    }

    // write output: out[b][i*64+j][h] + b2
    float* outp = out + (size_t)b * (Kk * Kk * Hh);
#pragma unroll
    for (int mt = 0; mt < 2; ++mt) {
#pragma unroll
        for (int nt = 0; nt < 8; ++nt) {
            int r0 = wm * 32 + mt * 16 + g;
            int r1 = r0 + 8;
            int c0 = wn * 64 + nt * 8 + 2 * q;
            float2 bv = __ldg((const float2*)&b2[c0]);
            int p0 = (I0 + (r0 >> 3)) * 64 + (J0 + (r0 & 7));
            int p1 = (I0 + (r1 >> 3)) * 64 + (J0 + (r1 & 7));
            float2 v0 = make_float2(oacc[mt][nt][0] + bv.x, oacc[mt][nt][1] + bv.y);
            float2 v1 = make_float2(oacc[mt][nt][2] + bv.x, oacc[mt][nt][3] + bv.y);
            *(float2*)&outp[(size_t)p0 * 256 + c0] = v0;
            *(float2*)&outp[(size_t)p1 * 256 + c0] = v1;
        }
    }
}

// ---------------------------------------------------------------------------
extern "C" void kernel_launch(void* const* d_in, const int* in_sizes, int n_in,
                              void* d_out, int out_size) {
    const float* cand = (const float*)d_in[0];
    const float* tok  = (const float*)d_in[1];
    const float* W1   = (const float*)d_in[2];
    const float* b1   = (const float*)d_in[3];
    const float* W2   = (const float*)d_in[4];
    const float* b2   = (const float*)d_in[5];
    const int*   ids  = (const int*)d_in[6];
    float* out = (float*)d_out;

    ctx_kernel<<<Bb * Kk, Hh>>>(tok, ids);
    w1t_kernel<<<dim3(FFN / 32, 256 / 32), dim3(32, 8)>>>(W1);
    w2t_kernel<<<dim3(Hh / 32, FFN / 32), dim3(32, 8)>>>(W2);
    phpt_kernel<<<dim3(FFN / 64, (Bb * Kk) / 64, 2), 128>>>(cand, W1, b1);

    const int smem_bytes = SMEM_WORDS * 4;  // 113664
    cudaFuncSetAttribute(pair_kernel, cudaFuncAttributeMaxDynamicSharedMemorySize, smem_bytes);
    pair_kernel<<<dim3(8, 8, 8), 256, smem_bytes>>>(b2, out);
}

// round 12
// speedup vs baseline: 2.0971x; 1.0156x over previous
#include <cuda_runtime.h>
#include <cuda_fp16.h>
#include <cstdint>

#define Bb  8
#define Kk  64
#define Ll  1024
#define Hh  256
#define FFN 3072
#define WIN 20
#define F   128
#define NCH (FFN / F)   // 24

// scratch (device globals — no runtime allocation allowed)
__device__ __align__(16) float  g_ctx[Bb * Kk * Hh];    // [B*K, H] window max
__device__ __align__(16) float  g_ph [Bb * Kk * FFN];   // head @ W1a + b1
__device__ __align__(16) float  g_pt [Bb * Kk * FFN];   // tail @ W1b
__device__ __align__(16) __half g_w1h[FFN * Hh];        // W1 ctx block transposed [n=3072][k=256] fp16
__device__ __align__(16) __half g_w2h[Hh * FFN];        // W2 transposed [n=256][k=3072] fp16

// fp16 m16n8k16
__device__ __forceinline__ void mma16(float d[4], const uint32_t a[4], const uint32_t b[2]) {
    asm volatile(
        "mma.sync.aligned.m16n8k16.row.col.f32.f16.f16.f32 "
        "{%0,%1,%2,%3}, {%4,%5,%6,%7}, {%8,%9}, {%0,%1,%2,%3};"
        : "+f"(d[0]), "+f"(d[1]), "+f"(d[2]), "+f"(d[3])
        : "r"(a[0]), "r"(a[1]), "r"(a[2]), "r"(a[3]), "r"(b[0]), "r"(b[1]));
}

__device__ __forceinline__ void cp16(uint32_t dst_smem, const void* src) {
    asm volatile("cp.async.cg.shared.global [%0], [%1], 16;" :: "r"(dst_smem), "l"(src));
}
__device__ __forceinline__ void cp_commit() { asm volatile("cp.async.commit_group;"); }
template <int N> __device__ __forceinline__ void cp_wait() {
    asm volatile("cp.async.wait_group %0;" :: "n"(N));
}

// ---------------------------------------------------------------------------
// Kernel 1: per-span window max over token_reps. grid = B*K, 256 threads.
// ---------------------------------------------------------------------------
__global__ void ctx_kernel(const float* __restrict__ tok,
                           const int* __restrict__ ids) {
    int bk = blockIdx.x;
    int b  = bk >> 6;
    int h  = threadIdx.x;
    int s  = ids[bk * 2 + 0];
    int e  = ids[bk * 2 + 1];

    float m = __int_as_float(0xff800000);

    int lo = s - WIN; if (lo < 0) lo = 0;
    for (int p = lo; p < s; ++p)
        m = fmaxf(m, tok[((size_t)b * Ll + p) * Hh + h]);

    int hi = e + WIN; if (hi > Ll - 1) hi = Ll - 1;
    for (int p = e + 1; p <= hi; ++p)
        m = fmaxf(m, tok[((size_t)b * Ll + p) * Hh + h]);

    g_ctx[(size_t)bk * Hh + h] = m;
}

// ---------------------------------------------------------------------------
// Prep A: transpose+convert W1 ctx block -> g_w1h[n][k] fp16. grid (96,8), blk (32,8)
// ---------------------------------------------------------------------------
__global__ void w1t_kernel(const float* __restrict__ W1) {
    __shared__ float tile[32][33];
    int n0 = blockIdx.x * 32, k0 = blockIdx.y * 32;
    int tx = threadIdx.x, ty = threadIdx.y;
#pragma unroll
    for (int r = 0; r < 4; ++r) {
        int k = ty + r * 8;
        tile[tx][k] = W1[(size_t)(512 + k0 + k) * FFN + n0 + tx];
    }
    __syncthreads();
#pragma unroll
    for (int r = 0; r < 4; ++r) {
        int n = ty + r * 8;
        g_w1h[(size_t)(n0 + n) * 256 + k0 + tx] = __float2half_rn(tile[n][tx]);
    }
}

// Prep B: transpose+convert W2 -> g_w2h[n=256][k=3072] fp16. grid (8,96), blk (32,8)
__global__ void w2t_kernel(const float* __restrict__ W2) {
    __shared__ float tile[32][33];
    int n0 = blockIdx.x * 32, k0 = blockIdx.y * 32;
    int tx = threadIdx.x, ty = threadIdx.y;
#pragma unroll
    for (int r = 0; r < 4; ++r) {
        int k = ty + r * 8;
        tile[tx][k] = W2[(size_t)(k0 + k) * Hh + n0 + tx];
    }
    __syncthreads();
#pragma unroll
    for (int r = 0; r < 4; ++r) {
        int n = ty + r * 8;
        g_w2h[(size_t)(n0 + n) * FFN + k0 + tx] = __float2half_rn(tile[n][tx]);
    }
}

// ---------------------------------------------------------------------------
// Kernel 2: Ph = cand @ W1[0:256] + b1 ; Pt = cand @ W1[256:512]  (fp16 mma)
// ---------------------------------------------------------------------------
__global__ __launch_bounds__(128) void phpt_kernel(const float* __restrict__ cand,
                                                   const float* __restrict__ W1,
                                                   const float* __restrict__ b1) {
    __shared__ uint32_t a_s[64 * 36];   // fp16 [64 m][64 k halves + pad]
    __shared__ uint32_t b_s[64 * 36];   // fp16 [64 n][64 k halves + pad]

    int tid = threadIdx.x;
    int w = tid >> 5, lane = tid & 31;
    int g = lane >> 2, q = lane & 3;
    int wm = w >> 1, wn = w & 1;
    int n0 = blockIdx.x * 64;
    int m0 = blockIdx.y * 64;
    int s  = blockIdx.z;

    float acc[2][4][4];
#pragma unroll
    for (int mt = 0; mt < 2; ++mt)
#pragma unroll
        for (int nt = 0; nt < 4; ++nt)
#pragma unroll
            for (int r = 0; r < 4; ++r) acc[mt][nt][r] = 0.f;

    for (int kc = 0; kc < 256; kc += 64) {
        __syncthreads();
#pragma unroll
        for (int it = 0; it < 16; ++it) {
            int idx = it * 128 + tid;              // 2048 words
            int m = idx >> 5, ww = idx & 31;
            float2 v = *(const float2*)&cand[(size_t)(m0 + m) * 256 + kc + 2 * ww];
            __half2 h = __floats2half2_rn(v.x, v.y);
            a_s[m * 36 + ww] = *(uint32_t*)&h;
        }
#pragma unroll
        for (int it = 0; it < 16; ++it) {
            int idx = it * 128 + tid;
            int n = idx & 63, ww = idx >> 6;
            float v0 = W1[(size_t)(s * 256 + kc + 2 * ww) * FFN + n0 + n];
            float v1 = W1[(size_t)(s * 256 + kc + 2 * ww + 1) * FFN + n0 + n];
            __half2 h = __floats2half2_rn(v0, v1);
            b_s[n * 36 + ww] = *(uint32_t*)&h;
        }
        __syncthreads();

#pragma unroll
        for (int ks = 0; ks < 32; ks += 8) {       // 4 k16 steps
            uint32_t a[2][4], bb[4][2];
#pragma unroll
            for (int mt = 0; mt < 2; ++mt) {
                int r = wm * 32 + mt * 16 + g;
                a[mt][0] = a_s[r * 36 + ks + q];
                a[mt][1] = a_s[(r + 8) * 36 + ks + q];
                a[mt][2] = a_s[r * 36 + ks + q + 4];
                a[mt][3] = a_s[(r + 8) * 36 + ks + q + 4];
            }
#pragma unroll
            for (int nt = 0; nt < 4; ++nt) {
                int c = wn * 32 + nt * 8 + g;
                bb[nt][0] = b_s[c * 36 + ks + q];
                bb[nt][1] = b_s[c * 36 + ks + q + 4];
            }
#pragma unroll
            for (int mt = 0; mt < 2; ++mt)
#pragma unroll
                for (int nt = 0; nt < 4; ++nt)
                    mma16(acc[mt][nt], a[mt], bb[nt]);
        }
    }

    float* out = s ? g_pt : g_ph;
#pragma unroll
    for (int mt = 0; mt < 2; ++mt) {
#pragma unroll
        for (int nt = 0; nt < 4; ++nt) {
            int r0 = m0 + wm * 32 + mt * 16 + g;
            int c0 = n0 + wn * 32 + nt * 8 + 2 * q;
            float bias0 = s ? 0.f : b1[c0];
            float bias1 = s ? 0.f : b1[c0 + 1];
            float2 v0 = make_float2(acc[mt][nt][0] + bias0, acc[mt][nt][1] + bias1);
            float2 v1 = make_float2(acc[mt][nt][2] + bias0, acc[mt][nt][3] + bias1);
            *(float2*)&out[(size_t)r0 * FFN + c0] = v0;
            *(float2*)&out[(size_t)(r0 + 8) * FFN + c0] = v1;
        }
    }
}

// ---------------------------------------------------------------------------
// Kernel 3: fp16 fused pairwise kernel. 256 threads / 8 warps (2m x 4n), F=128.
// ph/pt/b2 via __ldg (L2-resident), no SMEM staging for them.
// SMEM (words): ctxA 64x132 @0 | w1b 128x132 @8448 | w2s 256x68 @25344
//               | hs 64x68 @42752  -> 47104 words = 188416 B.
// ---------------------------------------------------------------------------
#define CTXA_W 0
#define W1B_W  8448
#define W2S_W  25344
#define HS_W   42752
#define SMEM_WORDS 47104

__global__ __launch_bounds__(256, 1) void pair_kernel(const float* __restrict__ b2,
                                                      float* __restrict__ out) {
    extern __shared__ __align__(16) uint32_t sm[];
    uint32_t* ctxA = sm + CTXA_W;   // fp16 [64][264 halves] as words (stride 132)
    uint32_t* w1b  = sm + W1B_W;    // fp16 [128 n][264 halves]
    uint32_t* w2s  = sm + W2S_W;    // fp16 [256 n][136 halves] (stride 68)
    uint32_t* hs   = sm + HS_W;     // fp16 [64][136 halves]

    const uint32_t w1b_u = (uint32_t)__cvta_generic_to_shared(w1b);
    const uint32_t w2s_u = (uint32_t)__cvta_generic_to_shared(w2s);

    int tid = threadIdx.x;
    int w = tid >> 5, lane = tid & 31;
    int g = lane >> 2, q = lane & 3;
    int wm = w >> 2;    // 0..1
    int wn = w & 3;     // 0..3
    int b  = blockIdx.z;
    int I0 = blockIdx.y * 8;
    int J0 = blockIdx.x * 8;

    const float* phbase = g_ph + (size_t)(b * Kk + I0) * FFN;
    const float* ptbase = g_pt + (size_t)(b * Kk + J0) * FFN;

    // --- staging helpers (16B cp.async, fp16 payloads) ---
    auto stage_w1 = [&](int fc) {              // [128 n][256 k halves], stride 132 words
#pragma unroll
        for (int i = 0; i < 16; ++i) {
            int idx = i * 256 + tid;           // 4096 x 16B
            int n = idx >> 5, k8 = (idx & 31) << 3;
            cp16(w1b_u + (uint32_t)(n * 132 + (k8 >> 1)) * 4,
                 g_w1h + (size_t)(fc + n) * 256 + k8);
        }
    };
    auto stage_w2 = [&](int fc) {              // [256 n][128 k halves], stride 68 words
#pragma unroll
        for (int i = 0; i < 16; ++i) {
            int idx = i * 256 + tid;           // 4096 x 16B
            int n = idx >> 4, k8 = (idx & 15) << 3;
            cp16(w2s_u + (uint32_t)(n * 68 + (k8 >> 1)) * 4,
                 g_w2h + (size_t)n * FFN + fc + k8);
        }
    };

    // prefetch chunk 0: G1 = {w1}, G2 = {w2}
    stage_w1(0); cp_commit();
    stage_w2(0); cp_commit();

    // build ctxA[r][k] fp16 = max(ctx_i, ctx_j), r = ii*8 + jj, stride 132 words
    const float* ctxb = g_ctx + (size_t)b * Kk * Hh;
    for (int idx = tid; idx < 64 * 64; idx += 256) {
        int r = idx >> 6, k4 = (idx & 63) << 2;
        float4 va = *(const float4*)&ctxb[(I0 + (r >> 3)) * 256 + k4];
        float4 vb = *(const float4*)&ctxb[(J0 + (r & 7)) * 256 + k4];
        __half2 h0 = __floats2half2_rn(fmaxf(va.x, vb.x), fmaxf(va.y, vb.y));
        __half2 h1 = __floats2half2_rn(fmaxf(va.z, vb.z), fmaxf(va.w, vb.w));
        uint32_t* dst = &ctxA[r * 132 + (k4 >> 1)];
        dst[0] = *(uint32_t*)&h0;
        dst[1] = *(uint32_t*)&h1;
    }

    float oacc[2][8][4];
#pragma unroll
    for (int mt = 0; mt < 2; ++mt)
#pragma unroll
        for (int nt = 0; nt < 8; ++nt)
#pragma unroll
            for (int r = 0; r < 4; ++r) oacc[mt][nt][r] = 0.f;

    const int rA0 = wm * 32 + g;
    const int jj  = g;

    for (int c = 0; c < NCH; ++c) {
        int fc  = c * F;
        int fcn = (c < NCH - 1) ? fc + F : 0;

        cp_wait<1>();          // G1_c landed (w1)
        __syncthreads();       // + ctxA/hs hazards

        // prefetch ph/pt for this chunk's epilogue (L2-resident, covered by GEMM1)
        float2 phv[2][2][4], ptv[4];
#pragma unroll
        for (int mt = 0; mt < 2; ++mt) {
            int ii = 4 * wm + 2 * mt;
#pragma unroll
            for (int nt = 0; nt < 4; ++nt) {
                int col = fc + wn * 32 + nt * 8 + 2 * q;
                phv[mt][0][nt] = __ldg((const float2*)&phbase[(size_t)ii * FFN + col]);
                phv[mt][1][nt] = __ldg((const float2*)&phbase[(size_t)(ii + 1) * FFN + col]);
            }
        }
#pragma unroll
        for (int nt = 0; nt < 4; ++nt)
            ptv[nt] = __ldg((const float2*)&ptbase[(size_t)jj * FFN + fc + wn * 32 + nt * 8 + 2 * q]);

        // ---- GEMM1: [64 x 128] = ctxA[64x256] @ w1^T, 16 k16-steps ----
        float c1[2][4][4];
#pragma unroll
        for (int mt = 0; mt < 2; ++mt)
#pragma unroll
            for (int nt = 0; nt < 4; ++nt)
#pragma unroll
                for (int r = 0; r < 4; ++r) c1[mt][nt][r] = 0.f;

#pragma unroll
        for (int i = 0; i < 16; ++i) {
            int kb = i * 8;
            uint32_t a[2][4], bb[4][2];
#pragma unroll
            for (int mt = 0; mt < 2; ++mt) {
                int r = rA0 + mt * 16;
                a[mt][0] = ctxA[r * 132 + kb + q];
                a[mt][1] = ctxA[(r + 8) * 132 + kb + q];
                a[mt][2] = ctxA[r * 132 + kb + q + 4];
                a[mt][3] = ctxA[(r + 8) * 132 + kb + q + 4];
            }
#pragma unroll
            for (int nt = 0; nt < 4; ++nt) {
                int cc = wn * 32 + nt * 8 + g;
                bb[nt][0] = w1b[cc * 132 + kb + q];
                bb[nt][1] = w1b[cc * 132 + kb + q + 4];
            }
#pragma unroll
            for (int mt = 0; mt < 2; ++mt)
#pragma unroll
                for (int nt = 0; nt < 4; ++nt)
                    mma16(c1[mt][nt], a[mt], bb[nt]);
        }

        // epilogue: h = relu(C1 + Ph_i + Pt_j) -> hs fp16 (stride 68 words)
#pragma unroll
        for (int mt = 0; mt < 2; ++mt) {
#pragma unroll
            for (int nt = 0; nt < 4; ++nt) {
                int r0 = wm * 32 + mt * 16 + g;
                int r1 = r0 + 8;
                int c0 = wn * 32 + nt * 8 + 2 * q;   // col within [0,128)
                float2 ph0 = phv[mt][0][nt];
                float2 ph1 = phv[mt][1][nt];
                float2 pt  = ptv[nt];
                float h00 = fmaxf(c1[mt][nt][0] + ph0.x + pt.x, 0.f);
                float h01 = fmaxf(c1[mt][nt][1] + ph0.y + pt.y, 0.f);
                float h10 = fmaxf(c1[mt][nt][2] + ph1.x + pt.x, 0.f);
                float h11 = fmaxf(c1[mt][nt][3] + ph1.y + pt.y, 0.f);
                __half2 p0 = __floats2half2_rn(h00, h01);
                __half2 p1 = __floats2half2_rn(h10, h11);
                hs[r0 * 68 + (c0 >> 1)] = *(uint32_t*)&p0;
                hs[r1 * 68 + (c0 >> 1)] = *(uint32_t*)&p1;
            }
        }

        cp_wait<0>();          // G2_c landed (w2)
        __syncthreads();       // hs visible; w1 free
        stage_w1(fcn); cp_commit();   // G1_{c+1} (overlaps GEMM2)

        // ---- GEMM2: out[64x256] += hs[64x128] @ w2^T, 8 k16-steps ----
#pragma unroll
        for (int i = 0; i < 8; ++i) {
            int kb = i * 8;
            uint32_t a[2][4];
#pragma unroll
            for (int mt = 0; mt < 2; ++mt) {
                int r = rA0 + mt * 16;
                a[mt][0] = hs[r * 68 + kb + q];
                a[mt][1] = hs[(r + 8) * 68 + kb + q];
                a[mt][2] = hs[r * 68 + kb + q + 4];
                a[mt][3] = hs[(r + 8) * 68 + kb + q + 4];
            }
#pragma unroll
            for (int nt = 0; nt < 8; ++nt) {
                int cc = wn * 64 + nt * 8 + g;
                uint32_t bb[2];
                bb[0] = w2s[cc * 68 + kb + q];
                bb[1] = w2s[cc * 68 + kb + q + 4];
#pragma unroll
                for (int mt = 0; mt < 2; ++mt)
                    mma16(oacc[mt][nt], a[mt], bb);
            }
        }

        __syncthreads();       // everyone done reading w2s + hs
        stage_w2(fcn); cp_commit();   // G2_{c+1}
    }

    // write output: out[b][i*64+j][h] + b2
    float* outp = out + (size_t)b * (Kk * Kk * Hh);
#pragma unroll
    for (int mt = 0; mt < 2; ++mt) {
#pragma unroll
        for (int nt = 0; nt < 8; ++nt) {
            int r0 = wm * 32 + mt * 16 + g;
            int r1 = r0 + 8;
            int c0 = wn * 64 + nt * 8 + 2 * q;
            float2 bv = __ldg((const float2*)&b2[c0]);
            int p0 = (I0 + (r0 >> 3)) * 64 + (J0 + (r0 & 7));
            int p1 = (I0 + (r1 >> 3)) * 64 + (J0 + (r1 & 7));
            float2 v0 = make_float2(oacc[mt][nt][0] + bv.x, oacc[mt][nt][1] + bv.y);
            float2 v1 = make_float2(oacc[mt][nt][2] + bv.x, oacc[mt][nt][3] + bv.y);
            *(float2*)&outp[(size_t)p0 * 256 + c0] = v0;
            *(float2*)&outp[(size_t)p1 * 256 + c0] = v1;
        }
    }
}

// ---------------------------------------------------------------------------
extern "C" void kernel_launch(void* const* d_in, const int* in_sizes, int n_in,
                              void* d_out, int out_size) {
    const float* cand = (const float*)d_in[0];
    const float* tok  = (const float*)d_in[1];
    const float* W1   = (const float*)d_in[2];
    const float* b1   = (const float*)d_in[3];
    const float* W2   = (const float*)d_in[4];
    const float* b2   = (const float*)d_in[5];
    const int*   ids  = (const int*)d_in[6];
    float* out = (float*)d_out;

    ctx_kernel<<<Bb * Kk, Hh>>>(tok, ids);
    w1t_kernel<<<dim3(FFN / 32, 256 / 32), dim3(32, 8)>>>(W1);
    w2t_kernel<<<dim3(Hh / 32, FFN / 32), dim3(32, 8)>>>(W2);
    phpt_kernel<<<dim3(FFN / 64, (Bb * Kk) / 64, 2), 128>>>(cand, W1, b1);

    const int smem_bytes = SMEM_WORDS * 4;  // 188416
    cudaFuncSetAttribute(pair_kernel, cudaFuncAttributeMaxDynamicSharedMemorySize, smem_bytes);
    pair_kernel<<<dim3(8, 8, 8), 256, smem_bytes>>>(b2, out);
}

// round 13
// speedup vs baseline: 2.1259x; 1.0137x over previous
#include <cuda_runtime.h>
#include <cuda_fp16.h>
#include <cstdint>

#define Bb  8
#define Kk  64
#define Ll  1024
#define Hh  256
#define FFN 3072
#define WIN 20
#define F   128
#define NCH (FFN / F)   // 24

// scratch (device globals — no runtime allocation allowed)
__device__ __align__(16) float  g_ctx[Bb * Kk * Hh];    // [B*K, H] window max
__device__ __align__(16) float  g_ph [Bb * Kk * FFN];   // head @ W1a + b1
__device__ __align__(16) float  g_pt [Bb * Kk * FFN];   // tail @ W1b
__device__ __align__(16) __half g_w1h[FFN * 768];       // ALL of W1 transposed [n=3072][k=768] fp16
__device__ __align__(16) __half g_w2h[Hh * FFN];        // W2 transposed [n=256][k=3072] fp16
__device__ __align__(16) __half g_candh[Bb * Kk * Hh];  // cand fp16 [512][256]

// fp16 m16n8k16
__device__ __forceinline__ void mma16(float d[4], const uint32_t a[4], const uint32_t b[2]) {
    asm volatile(
        "mma.sync.aligned.m16n8k16.row.col.f32.f16.f16.f32 "
        "{%0,%1,%2,%3}, {%4,%5,%6,%7}, {%8,%9}, {%0,%1,%2,%3};"
        : "+f"(d[0]), "+f"(d[1]), "+f"(d[2]), "+f"(d[3])
        : "r"(a[0]), "r"(a[1]), "r"(a[2]), "r"(a[3]), "r"(b[0]), "r"(b[1]));
}

__device__ __forceinline__ void cp16(uint32_t dst_smem, const void* src) {
    asm volatile("cp.async.cg.shared.global [%0], [%1], 16;" :: "r"(dst_smem), "l"(src));
}
__device__ __forceinline__ void cp_commit() { asm volatile("cp.async.commit_group;"); }
template <int N> __device__ __forceinline__ void cp_wait() {
    asm volatile("cp.async.wait_group %0;" :: "n"(N));
}

// ---------------------------------------------------------------------------
// Kernel 1: per-span window max over token_reps. grid = B*K, 256 threads.
// ---------------------------------------------------------------------------
__global__ void ctx_kernel(const float* __restrict__ tok,
                           const int* __restrict__ ids) {
    int bk = blockIdx.x;
    int b  = bk >> 6;
    int h  = threadIdx.x;
    int s  = ids[bk * 2 + 0];
    int e  = ids[bk * 2 + 1];

    float m = __int_as_float(0xff800000);

    int lo = s - WIN; if (lo < 0) lo = 0;
    for (int p = lo; p < s; ++p)
        m = fmaxf(m, tok[((size_t)b * Ll + p) * Hh + h]);

    int hi = e + WIN; if (hi > Ll - 1) hi = Ll - 1;
    for (int p = e + 1; p <= hi; ++p)
        m = fmaxf(m, tok[((size_t)b * Ll + p) * Hh + h]);

    g_ctx[(size_t)bk * Hh + h] = m;
}

// ---------------------------------------------------------------------------
// Prep A: transpose+convert ALL of W1 -> g_w1h[n][k=768] fp16.
// grid (96, 24), blk (32, 8). 32x32 tiles.
// ---------------------------------------------------------------------------
__global__ void w1t_kernel(const float* __restrict__ W1) {
    __shared__ float tile[32][33];
    int n0 = blockIdx.x * 32, k0 = blockIdx.y * 32;
    int tx = threadIdx.x, ty = threadIdx.y;
#pragma unroll
    for (int r = 0; r < 4; ++r) {
        int k = ty + r * 8;
        tile[tx][k] = W1[(size_t)(k0 + k) * FFN + n0 + tx];
    }
    __syncthreads();
#pragma unroll
    for (int r = 0; r < 4; ++r) {
        int n = ty + r * 8;
        g_w1h[(size_t)(n0 + n) * 768 + k0 + tx] = __float2half_rn(tile[n][tx]);
    }
}

// Prep B: transpose+convert W2 -> g_w2h[n=256][k=3072] fp16. grid (8,96), blk (32,8)
__global__ void w2t_kernel(const float* __restrict__ W2) {
    __shared__ float tile[32][33];
    int n0 = blockIdx.x * 32, k0 = blockIdx.y * 32;
    int tx = threadIdx.x, ty = threadIdx.y;
#pragma unroll
    for (int r = 0; r < 4; ++r) {
        int k = ty + r * 8;
        tile[tx][k] = W2[(size_t)(k0 + k) * Hh + n0 + tx];
    }
    __syncthreads();
#pragma unroll
    for (int r = 0; r < 4; ++r) {
        int n = ty + r * 8;
        g_w2h[(size_t)(n0 + n) * FFN + k0 + tx] = __float2half_rn(tile[n][tx]);
    }
}

// Prep C: convert cand -> fp16 [512][256]. grid 128, 256 thr (1 float4 each).
__global__ void candh_kernel(const float* __restrict__ cand) {
    int i = blockIdx.x * 256 + threadIdx.x;   // float4 index, 32768 total
    float4 v = ((const float4*)cand)[i];
    __half2 h0 = __floats2half2_rn(v.x, v.y);
    __half2 h1 = __floats2half2_rn(v.z, v.w);
    uint32_t t[2] = { *(uint32_t*)&h0, *(uint32_t*)&h1 };
    ((uint2*)g_candh)[i] = *(uint2*)t;
}

// ---------------------------------------------------------------------------
// Kernel 2 v2: Ph/Pt GEMM, full-K resident. grid (24, 8, 2), 256 threads.
// Tile 64m x 128n, K=256 staged once via cp.async. occ 2 (101KB SMEM).
//   s=0: Ph = cand @ W1[0:256]^T(+b1)   s=1: Pt = cand @ W1[256:512]^T
// SMEM (words): a_s 64x132 @0 | b_s 128x132 @8448 -> 25344 w = 101376 B
// ---------------------------------------------------------------------------
__global__ __launch_bounds__(256, 2) void phpt_kernel(const float* __restrict__ b1,
                                                      float* __restrict__ /*unused*/) {
    extern __shared__ __align__(16) uint32_t psm[];
    uint32_t* a_s = psm;            // fp16 [64 m][264 halves] stride 132
    uint32_t* b_s = psm + 8448;     // fp16 [128 n][264 halves] stride 132

    const uint32_t a_u = (uint32_t)__cvta_generic_to_shared(a_s);
    const uint32_t b_u = (uint32_t)__cvta_generic_to_shared(b_s);

    int tid = threadIdx.x;
    int w = tid >> 5, lane = tid & 31;
    int g = lane >> 2, q = lane & 3;
    int wm = w >> 2;    // 0..1
    int wn = w & 3;     // 0..3
    int n0 = blockIdx.x * 128;
    int m0 = blockIdx.y * 64;
    int s  = blockIdx.z;

    // stage A [64 m][256 k halves]: 2048 x 16B -> 8 per thread
#pragma unroll
    for (int i = 0; i < 8; ++i) {
        int idx = i * 256 + tid;
        int m = idx >> 5, k8 = (idx & 31) << 3;
        cp16(a_u + (uint32_t)(m * 132 + (k8 >> 1)) * 4,
             g_candh + (size_t)(m0 + m) * 256 + k8);
    }
    // stage B [128 n][256 k halves] from g_w1h rows, k-offset s*256: 4096 x 16B
#pragma unroll
    for (int i = 0; i < 16; ++i) {
        int idx = i * 256 + tid;
        int n = idx >> 5, k8 = (idx & 31) << 3;
        cp16(b_u + (uint32_t)(n * 132 + (k8 >> 1)) * 4,
             g_w1h + (size_t)(n0 + n) * 768 + s * 256 + k8);
    }
    cp_commit();
    cp_wait<0>();
    __syncthreads();

    float acc[2][4][4];
#pragma unroll
    for (int mt = 0; mt < 2; ++mt)
#pragma unroll
        for (int nt = 0; nt < 4; ++nt)
#pragma unroll
            for (int r = 0; r < 4; ++r) acc[mt][nt][r] = 0.f;

    const int rA0 = wm * 32 + g;
#pragma unroll
    for (int i = 0; i < 16; ++i) {
        int kb = i * 8;
        uint32_t a[2][4], bb[4][2];
#pragma unroll
        for (int mt = 0; mt < 2; ++mt) {
            int r = rA0 + mt * 16;
            a[mt][0] = a_s[r * 132 + kb + q];
            a[mt][1] = a_s[(r + 8) * 132 + kb + q];
            a[mt][2] = a_s[r * 132 + kb + q + 4];
            a[mt][3] = a_s[(r + 8) * 132 + kb + q + 4];
        }
#pragma unroll
        for (int nt = 0; nt < 4; ++nt) {
            int cc = wn * 32 + nt * 8 + g;
            bb[nt][0] = b_s[cc * 132 + kb + q];
            bb[nt][1] = b_s[cc * 132 + kb + q + 4];
        }
#pragma unroll
        for (int mt = 0; mt < 2; ++mt)
#pragma unroll
            for (int nt = 0; nt < 4; ++nt)
                mma16(acc[mt][nt], a[mt], bb[nt]);
    }

    float* out = s ? g_pt : g_ph;
#pragma unroll
    for (int mt = 0; mt < 2; ++mt) {
#pragma unroll
        for (int nt = 0; nt < 4; ++nt) {
            int r0 = m0 + wm * 32 + mt * 16 + g;
            int c0 = n0 + wn * 32 + nt * 8 + 2 * q;
            float bias0 = s ? 0.f : __ldg(&b1[c0]);
            float bias1 = s ? 0.f : __ldg(&b1[c0 + 1]);
            float2 v0 = make_float2(acc[mt][nt][0] + bias0, acc[mt][nt][1] + bias1);
            float2 v1 = make_float2(acc[mt][nt][2] + bias0, acc[mt][nt][3] + bias1);
            *(float2*)&out[(size_t)r0 * FFN + c0] = v0;
            *(float2*)&out[(size_t)(r0 + 8) * FFN + c0] = v1;
        }
    }
}
#define PHPT_SMEM (25344 * 4)

// ---------------------------------------------------------------------------
// Kernel 3: fp16 fused pairwise kernel. 256 threads / 8 warps (2m x 4n), F=128.
// ph/pt/b2 via __ldg (L2-resident). (unchanged from R12 passing version,
// except w1 staging reads the k>=512 slice of g_w1h[n][768])
// SMEM (words): ctxA 64x132 @0 | w1b 128x132 @8448 | w2s 256x68 @25344
//               | hs 64x68 @42752  -> 47104 words = 188416 B.
// ---------------------------------------------------------------------------
#define CTXA_W 0
#define W1B_W  8448
#define W2S_W  25344
#define HS_W   42752
#define SMEM_WORDS 47104

__global__ __launch_bounds__(256, 1) void pair_kernel(const float* __restrict__ b2,
                                                      float* __restrict__ out) {
    extern __shared__ __align__(16) uint32_t sm[];
    uint32_t* ctxA = sm + CTXA_W;
    uint32_t* w1b  = sm + W1B_W;
    uint32_t* w2s  = sm + W2S_W;
    uint32_t* hs   = sm + HS_W;

    const uint32_t w1b_u = (uint32_t)__cvta_generic_to_shared(w1b);
    const uint32_t w2s_u = (uint32_t)__cvta_generic_to_shared(w2s);

    int tid = threadIdx.x;
    int w = tid >> 5, lane = tid & 31;
    int g = lane >> 2, q = lane & 3;
    int wm = w >> 2;    // 0..1
    int wn = w & 3;     // 0..3
    int b  = blockIdx.z;
    int I0 = blockIdx.y * 8;
    int J0 = blockIdx.x * 8;

    const float* phbase = g_ph + (size_t)(b * Kk + I0) * FFN;
    const float* ptbase = g_pt + (size_t)(b * Kk + J0) * FFN;

    auto stage_w1 = [&](int fc) {              // ctx block rows: k-offset 512
#pragma unroll
        for (int i = 0; i < 16; ++i) {
            int idx = i * 256 + tid;           // 4096 x 16B
            int n = idx >> 5, k8 = (idx & 31) << 3;
            cp16(w1b_u + (uint32_t)(n * 132 + (k8 >> 1)) * 4,
                 g_w1h + (size_t)(fc + n) * 768 + 512 + k8);
        }
    };
    auto stage_w2 = [&](int fc) {
#pragma unroll
        for (int i = 0; i < 16; ++i) {
            int idx = i * 256 + tid;           // 4096 x 16B
            int n = idx >> 4, k8 = (idx & 15) << 3;
            cp16(w2s_u + (uint32_t)(n * 68 + (k8 >> 1)) * 4,
                 g_w2h + (size_t)n * FFN + fc + k8);
        }
    };

    // prefetch chunk 0
    stage_w1(0); cp_commit();
    stage_w2(0); cp_commit();

    // build ctxA[r][k] fp16 = max(ctx_i, ctx_j), r = ii*8 + jj, stride 132 words
    const float* ctxb = g_ctx + (size_t)b * Kk * Hh;
    for (int idx = tid; idx < 64 * 64; idx += 256) {
        int r = idx >> 6, k4 = (idx & 63) << 2;
        float4 va = *(const float4*)&ctxb[(I0 + (r >> 3)) * 256 + k4];
        float4 vb = *(const float4*)&ctxb[(J0 + (r & 7)) * 256 + k4];
        __half2 h0 = __floats2half2_rn(fmaxf(va.x, vb.x), fmaxf(va.y, vb.y));
        __half2 h1 = __floats2half2_rn(fmaxf(va.z, vb.z), fmaxf(va.w, vb.w));
        uint32_t* dst = &ctxA[r * 132 + (k4 >> 1)];
        dst[0] = *(uint32_t*)&h0;
        dst[1] = *(uint32_t*)&h1;
    }

    float oacc[2][8][4];
#pragma unroll
    for (int mt = 0; mt < 2; ++mt)
#pragma unroll
        for (int nt = 0; nt < 8; ++nt)
#pragma unroll
            for (int r = 0; r < 4; ++r) oacc[mt][nt][r] = 0.f;

    const int rA0 = wm * 32 + g;
    const int jj  = g;

    for (int c = 0; c < NCH; ++c) {
        int fc  = c * F;
        int fcn = (c < NCH - 1) ? fc + F : 0;

        cp_wait<1>();          // G1_c landed (w1)
        __syncthreads();       // + ctxA/hs hazards

        float2 phv[2][2][4], ptv[4];
#pragma unroll
        for (int mt = 0; mt < 2; ++mt) {
            int ii = 4 * wm + 2 * mt;
#pragma unroll
            for (int nt = 0; nt < 4; ++nt) {
                int col = fc + wn * 32 + nt * 8 + 2 * q;
                phv[mt][0][nt] = __ldg((const float2*)&phbase[(size_t)ii * FFN + col]);
                phv[mt][1][nt] = __ldg((const float2*)&phbase[(size_t)(ii + 1) * FFN + col]);
            }
        }
#pragma unroll
        for (int nt = 0; nt < 4; ++nt)
            ptv[nt] = __ldg((const float2*)&ptbase[(size_t)jj * FFN + fc + wn * 32 + nt * 8 + 2 * q]);

        // ---- GEMM1: [64 x 128] = ctxA[64x256] @ w1^T, 16 k16-steps ----
        float c1[2][4][4];
#pragma unroll
        for (int mt = 0; mt < 2; ++mt)
#pragma unroll
            for (int nt = 0; nt < 4; ++nt)
#pragma unroll
                for (int r = 0; r < 4; ++r) c1[mt][nt][r] = 0.f;

#pragma unroll
        for (int i = 0; i < 16; ++i) {
            int kb = i * 8;
            uint32_t a[2][4], bb[4][2];
#pragma unroll
            for (int mt = 0; mt < 2; ++mt) {
                int r = rA0 + mt * 16;
                a[mt][0] = ctxA[r * 132 + kb + q];
                a[mt][1] = ctxA[(r + 8) * 132 + kb + q];
                a[mt][2] = ctxA[r * 132 + kb + q + 4];
                a[mt][3] = ctxA[(r + 8) * 132 + kb + q + 4];
            }
#pragma unroll
            for (int nt = 0; nt < 4; ++nt) {
                int cc = wn * 32 + nt * 8 + g;
                bb[nt][0] = w1b[cc * 132 + kb + q];
                bb[nt][1] = w1b[cc * 132 + kb + q + 4];
            }
#pragma unroll
            for (int mt = 0; mt < 2; ++mt)
#pragma unroll
                for (int nt = 0; nt < 4; ++nt)
                    mma16(c1[mt][nt], a[mt], bb[nt]);
        }

        // epilogue: h = relu(C1 + Ph_i + Pt_j) -> hs fp16 (stride 68 words)
#pragma unroll
        for (int mt = 0; mt < 2; ++mt) {
#pragma unroll
            for (int nt = 0; nt < 4; ++nt) {
                int r0 = wm * 32 + mt * 16 + g;
                int r1 = r0 + 8;
                int c0 = wn * 32 + nt * 8 + 2 * q;
                float2 ph0 = phv[mt][0][nt];
                float2 ph1 = phv[mt][1][nt];
                float2 pt  = ptv[nt];
                float h00 = fmaxf(c1[mt][nt][0] + ph0.x + pt.x, 0.f);
                float h01 = fmaxf(c1[mt][nt][1] + ph0.y + pt.y, 0.f);
                float h10 = fmaxf(c1[mt][nt][2] + ph1.x + pt.x, 0.f);
                float h11 = fmaxf(c1[mt][nt][3] + ph1.y + pt.y, 0.f);
                __half2 p0 = __floats2half2_rn(h00, h01);
                __half2 p1 = __floats2half2_rn(h10, h11);
                hs[r0 * 68 + (c0 >> 1)] = *(uint32_t*)&p0;
                hs[r1 * 68 + (c0 >> 1)] = *(uint32_t*)&p1;
            }
        }

        cp_wait<0>();          // G2_c landed (w2)
        __syncthreads();       // hs visible; w1 free
        stage_w1(fcn); cp_commit();   // G1_{c+1} (overlaps GEMM2)

        // ---- GEMM2: out[64x256] += hs[64x128] @ w2^T, 8 k16-steps ----
#pragma unroll
        for (int i = 0; i < 8; ++i) {
            int kb = i * 8;
            uint32_t a[2][4];
#pragma unroll
            for (int mt = 0; mt < 2; ++mt) {
                int r = rA0 + mt * 16;
                a[mt][0] = hs[r * 68 + kb + q];
                a[mt][1] = hs[(r + 8) * 68 + kb + q];
                a[mt][2] = hs[r * 68 + kb + q + 4];
                a[mt][3] = hs[(r + 8) * 68 + kb + q + 4];
            }
#pragma unroll
            for (int nt = 0; nt < 8; ++nt) {
                int cc = wn * 64 + nt * 8 + g;
                uint32_t bb[2];
                bb[0] = w2s[cc * 68 + kb + q];
                bb[1] = w2s[cc * 68 + kb + q + 4];
#pragma unroll
                for (int mt = 0; mt < 2; ++mt)
                    mma16(oacc[mt][nt], a[mt], bb);
            }
        }

        __syncthreads();       // everyone done reading w2s + hs
        stage_w2(fcn); cp_commit();   // G2_{c+1}
    }

    // write output: out[b][i*64+j][h] + b2
    float* outp = out + (size_t)b * (Kk * Kk * Hh);
#pragma unroll
    for (int mt = 0; mt < 2; ++mt) {
#pragma unroll
        for (int nt = 0; nt < 8; ++nt) {
            int r0 = wm * 32 + mt * 16 + g;
            int r1 = r0 + 8;
            int c0 = wn * 64 + nt * 8 + 2 * q;
            float2 bv = __ldg((const float2*)&b2[c0]);
            int p0 = (I0 + (r0 >> 3)) * 64 + (J0 + (r0 & 7));
            int p1 = (I0 + (r1 >> 3)) * 64 + (J0 + (r1 & 7));
            float2 v0 = make_float2(oacc[mt][nt][0] + bv.x, oacc[mt][nt][1] + bv.y);
            float2 v1 = make_float2(oacc[mt][nt][2] + bv.x, oacc[mt][nt][3] + bv.y);
            *(float2*)&outp[(size_t)p0 * 256 + c0] = v0;
            *(float2*)&outp[(size_t)p1 * 256 + c0] = v1;
        }
    }
}

// ---------------------------------------------------------------------------
extern "C" void kernel_launch(void* const* d_in, const int* in_sizes, int n_in,
                              void* d_out, int out_size) {
    const float* cand = (const float*)d_in[0];
    const float* tok  = (const float*)d_in[1];
    const float* W1   = (const float*)d_in[2];
    const float* b1   = (const float*)d_in[3];
    const float* W2   = (const float*)d_in[4];
    const float* b2   = (const float*)d_in[5];
    const int*   ids  = (const int*)d_in[6];
    float* out = (float*)d_out;

    ctx_kernel<<<Bb * Kk, Hh>>>(tok, ids);
    w1t_kernel<<<dim3(FFN / 32, 768 / 32), dim3(32, 8)>>>(W1);
    w2t_kernel<<<dim3(Hh / 32, FFN / 32), dim3(32, 8)>>>(W2);
    candh_kernel<<<128, 256>>>(cand);

    cudaFuncSetAttribute(phpt_kernel, cudaFuncAttributeMaxDynamicSharedMemorySize, PHPT_SMEM);
    phpt_kernel<<<dim3(FFN / 128, (Bb * Kk) / 64, 2), 256, PHPT_SMEM>>>(b1, nullptr);

    const int smem_bytes = SMEM_WORDS * 4;  // 188416
    cudaFuncSetAttribute(pair_kernel, cudaFuncAttributeMaxDynamicSharedMemorySize, smem_bytes);
    pair_kernel<<<dim3(8, 8, 8), 256, smem_bytes>>>(b2, out);
}

// round 14
// speedup vs baseline: 2.2695x; 1.0676x over previous
#include <cuda_runtime.h>
#include <cuda_fp16.h>
#include <cstdint>

#define Bb  8
#define Kk  64
#define Ll  1024
#define Hh  256
#define FFN 3072
#define WIN 20
#define F   128
#define NCH (FFN / F)   // 24

// scratch (device globals — no runtime allocation allowed)
__device__ __align__(16) float  g_ctx[Bb * Kk * Hh];    // [B*K, H] window max
__device__ __align__(16) float  g_ph [Bb * Kk * FFN];   // head @ W1a + b1
__device__ __align__(16) float  g_pt [Bb * Kk * FFN];   // tail @ W1b
__device__ __align__(16) __half g_w1h[FFN * 768];       // ALL of W1 transposed [n=3072][k=768] fp16
__device__ __align__(16) __half g_w2h[Hh * FFN];        // W2 transposed [n=256][k=3072] fp16
__device__ __align__(16) __half g_candh[Bb * Kk * Hh];  // cand fp16 [512][256]

// fp16 m16n8k16
__device__ __forceinline__ void mma16(float d[4], const uint32_t a[4], const uint32_t b[2]) {
    asm volatile(
        "mma.sync.aligned.m16n8k16.row.col.f32.f16.f16.f32 "
        "{%0,%1,%2,%3}, {%4,%5,%6,%7}, {%8,%9}, {%0,%1,%2,%3};"
        : "+f"(d[0]), "+f"(d[1]), "+f"(d[2]), "+f"(d[3])
        : "r"(a[0]), "r"(a[1]), "r"(a[2]), "r"(a[3]), "r"(b[0]), "r"(b[1]));
}

__device__ __forceinline__ void ldsm4(uint32_t r[4], uint32_t addr) {
    asm volatile("ldmatrix.sync.aligned.m8n8.x4.shared.b16 {%0,%1,%2,%3}, [%4];"
                 : "=r"(r[0]), "=r"(r[1]), "=r"(r[2]), "=r"(r[3]) : "r"(addr));
}

__device__ __forceinline__ void cp16(uint32_t dst_smem, const void* src) {
    asm volatile("cp.async.cg.shared.global [%0], [%1], 16;" :: "r"(dst_smem), "l"(src));
}
__device__ __forceinline__ void cp_commit() { asm volatile("cp.async.commit_group;"); }
template <int N> __device__ __forceinline__ void cp_wait() {
    asm volatile("cp.async.wait_group %0;" :: "n"(N));
}

// ---------------------------------------------------------------------------
// Kernel 1: per-span window max over token_reps. grid = B*K, 256 threads.
// ---------------------------------------------------------------------------
__global__ void ctx_kernel(const float* __restrict__ tok,
                           const int* __restrict__ ids) {
    int bk = blockIdx.x;
    int b  = bk >> 6;
    int h  = threadIdx.x;
    int s  = ids[bk * 2 + 0];
    int e  = ids[bk * 2 + 1];

    float m = __int_as_float(0xff800000);

    int lo = s - WIN; if (lo < 0) lo = 0;
    for (int p = lo; p < s; ++p)
        m = fmaxf(m, tok[((size_t)b * Ll + p) * Hh + h]);

    int hi = e + WIN; if (hi > Ll - 1) hi = Ll - 1;
    for (int p = e + 1; p <= hi; ++p)
        m = fmaxf(m, tok[((size_t)b * Ll + p) * Hh + h]);

    g_ctx[(size_t)bk * Hh + h] = m;
}

// ---------------------------------------------------------------------------
// Prep A: transpose+convert ALL of W1 -> g_w1h[n][k=768] fp16. grid (96,24), blk (32,8)
// ---------------------------------------------------------------------------
__global__ void w1t_kernel(const float* __restrict__ W1) {
    __shared__ float tile[32][33];
    int n0 = blockIdx.x * 32, k0 = blockIdx.y * 32;
    int tx = threadIdx.x, ty = threadIdx.y;
#pragma unroll
    for (int r = 0; r < 4; ++r) {
        int k = ty + r * 8;
        tile[tx][k] = W1[(size_t)(k0 + k) * FFN + n0 + tx];
    }
    __syncthreads();
#pragma unroll
    for (int r = 0; r < 4; ++r) {
        int n = ty + r * 8;
        g_w1h[(size_t)(n0 + n) * 768 + k0 + tx] = __float2half_rn(tile[n][tx]);
    }
}

// Prep B: transpose+convert W2 -> g_w2h[n=256][k=3072] fp16. grid (8,96), blk (32,8)
__global__ void w2t_kernel(const float* __restrict__ W2) {
    __shared__ float tile[32][33];
    int n0 = blockIdx.x * 32, k0 = blockIdx.y * 32;
    int tx = threadIdx.x, ty = threadIdx.y;
#pragma unroll
    for (int r = 0; r < 4; ++r) {
        int k = ty + r * 8;
        tile[tx][k] = W2[(size_t)(k0 + k) * Hh + n0 + tx];
    }
    __syncthreads();
#pragma unroll
    for (int r = 0; r < 4; ++r) {
        int n = ty + r * 8;
        g_w2h[(size_t)(n0 + n) * FFN + k0 + tx] = __float2half_rn(tile[n][tx]);
    }
}

// Prep C: convert cand -> fp16 [512][256]. grid 128, 256 thr.
__global__ void candh_kernel(const float* __restrict__ cand) {
    int i = blockIdx.x * 256 + threadIdx.x;
    float4 v = ((const float4*)cand)[i];
    __half2 h0 = __floats2half2_rn(v.x, v.y);
    __half2 h1 = __floats2half2_rn(v.z, v.w);
    uint32_t t[2] = { *(uint32_t*)&h0, *(uint32_t*)&h1 };
    ((uint2*)g_candh)[i] = *(uint2*)t;
}

// ---------------------------------------------------------------------------
// Kernel 2 v2: Ph/Pt GEMM, full-K resident. grid (24, 8, 2), 256 threads, occ 2.
// SMEM (words): a_s 64x132 @0 | b_s 128x132 @8448 -> 25344 w = 101376 B
// ---------------------------------------------------------------------------
__global__ __launch_bounds__(256, 2) void phpt_kernel(const float* __restrict__ b1,
                                                      float* __restrict__ /*unused*/) {
    extern __shared__ __align__(16) uint32_t psm[];
    uint32_t* a_s = psm;
    uint32_t* b_s = psm + 8448;

    const uint32_t a_u = (uint32_t)__cvta_generic_to_shared(a_s);
    const uint32_t b_u = (uint32_t)__cvta_generic_to_shared(b_s);

    int tid = threadIdx.x;
    int w = tid >> 5, lane = tid & 31;
    int g = lane >> 2, q = lane & 3;
    int wm = w >> 2;
    int wn = w & 3;
    int n0 = blockIdx.x * 128;
    int m0 = blockIdx.y * 64;
    int s  = blockIdx.z;

#pragma unroll
    for (int i = 0; i < 8; ++i) {
        int idx = i * 256 + tid;
        int m = idx >> 5, k8 = (idx & 31) << 3;
        cp16(a_u + (uint32_t)(m * 132 + (k8 >> 1)) * 4,
             g_candh + (size_t)(m0 + m) * 256 + k8);
    }
#pragma unroll
    for (int i = 0; i < 16; ++i) {
        int idx = i * 256 + tid;
        int n = idx >> 5, k8 = (idx & 31) << 3;
        cp16(b_u + (uint32_t)(n * 132 + (k8 >> 1)) * 4,
             g_w1h + (size_t)(n0 + n) * 768 + s * 256 + k8);
    }
    cp_commit();
    cp_wait<0>();
    __syncthreads();

    // ldmatrix lane offsets (words)
    int lrow = lane & 7;
    int lsel8 = (lane >> 3) & 1;    // +8 rows (A) / +4 kwords (B)
    int lsel16 = lane >> 4;         // +4 kwords (A) / +8 cols (B)
    uint32_t aoff[2], boff[2];
#pragma unroll
    for (int mt = 0; mt < 2; ++mt)
        aoff[mt] = (uint32_t)((wm * 32 + mt * 16 + lrow + lsel8 * 8) * 132 + lsel16 * 4);
#pragma unroll
    for (int p = 0; p < 2; ++p)
        boff[p] = (uint32_t)((wn * 32 + p * 16 + lsel16 * 8 + lrow) * 132 + lsel8 * 4);

    float acc[2][4][4];
#pragma unroll
    for (int mt = 0; mt < 2; ++mt)
#pragma unroll
        for (int nt = 0; nt < 4; ++nt)
#pragma unroll
            for (int r = 0; r < 4; ++r) acc[mt][nt][r] = 0.f;

#pragma unroll
    for (int i = 0; i < 16; ++i) {
        int kb = i * 8;
        uint32_t a[2][4], bp[2][4];
#pragma unroll
        for (int mt = 0; mt < 2; ++mt) ldsm4(a[mt], a_u + (aoff[mt] + kb) * 4);
#pragma unroll
        for (int p = 0; p < 2; ++p) ldsm4(bp[p], b_u + (boff[p] + kb) * 4);
#pragma unroll
        for (int mt = 0; mt < 2; ++mt)
#pragma unroll
            for (int nt = 0; nt < 4; ++nt) {
                uint32_t bb[2] = { bp[nt >> 1][(nt & 1) * 2], bp[nt >> 1][(nt & 1) * 2 + 1] };
                mma16(acc[mt][nt], a[mt], bb);
            }
    }

    float* out = s ? g_pt : g_ph;
#pragma unroll
    for (int mt = 0; mt < 2; ++mt) {
#pragma unroll
        for (int nt = 0; nt < 4; ++nt) {
            int r0 = m0 + wm * 32 + mt * 16 + g;
            int c0 = n0 + wn * 32 + nt * 8 + 2 * q;
            float bias0 = s ? 0.f : __ldg(&b1[c0]);
            float bias1 = s ? 0.f : __ldg(&b1[c0 + 1]);
            float2 v0 = make_float2(acc[mt][nt][0] + bias0, acc[mt][nt][1] + bias1);
            float2 v1 = make_float2(acc[mt][nt][2] + bias0, acc[mt][nt][3] + bias1);
            *(float2*)&out[(size_t)r0 * FFN + c0] = v0;
            *(float2*)&out[(size_t)(r0 + 8) * FFN + c0] = v1;
        }
    }
}
#define PHPT_SMEM (25344 * 4)

// ---------------------------------------------------------------------------
// Kernel 3: fp16 fused pairwise kernel, ldmatrix fragments. 256 thr, F=128.
// SMEM (words): ctxA 64x132 @0 | w1b 128x132 @8448 | w2s 256x68 @25344
//               | hs 64x68 @42752  -> 47104 words = 188416 B.
// ---------------------------------------------------------------------------
#define CTXA_W 0
#define W1B_W  8448
#define W2S_W  25344
#define HS_W   42752
#define SMEM_WORDS 47104

__global__ __launch_bounds__(256, 1) void pair_kernel(const float* __restrict__ b2,
                                                      float* __restrict__ out) {
    extern __shared__ __align__(16) uint32_t sm[];
    uint32_t* ctxA = sm + CTXA_W;
    uint32_t* hs   = sm + HS_W;

    const uint32_t ctxA_u = (uint32_t)__cvta_generic_to_shared(sm + CTXA_W);
    const uint32_t w1b_u  = (uint32_t)__cvta_generic_to_shared(sm + W1B_W);
    const uint32_t w2s_u  = (uint32_t)__cvta_generic_to_shared(sm + W2S_W);
    const uint32_t hs_u   = (uint32_t)__cvta_generic_to_shared(sm + HS_W);

    int tid = threadIdx.x;
    int w = tid >> 5, lane = tid & 31;
    int g = lane >> 2, q = lane & 3;
    int wm = w >> 2;    // 0..1
    int wn = w & 3;     // 0..3
    int b  = blockIdx.z;
    int I0 = blockIdx.y * 8;
    int J0 = blockIdx.x * 8;

    const float* phbase = g_ph + (size_t)(b * Kk + I0) * FFN;
    const float* ptbase = g_pt + (size_t)(b * Kk + J0) * FFN;

    auto stage_w1 = [&](int fc) {
#pragma unroll
        for (int i = 0; i < 16; ++i) {
            int idx = i * 256 + tid;
            int n = idx >> 5, k8 = (idx & 31) << 3;
            cp16(w1b_u + (uint32_t)(n * 132 + (k8 >> 1)) * 4,
                 g_w1h + (size_t)(fc + n) * 768 + 512 + k8);
        }
    };
    auto stage_w2 = [&](int fc) {
#pragma unroll
        for (int i = 0; i < 16; ++i) {
            int idx = i * 256 + tid;
            int n = idx >> 4, k8 = (idx & 15) << 3;
            cp16(w2s_u + (uint32_t)(n * 68 + (k8 >> 1)) * 4,
                 g_w2h + (size_t)n * FFN + fc + k8);
        }
    };

    stage_w1(0); cp_commit();
    stage_w2(0); cp_commit();

    // build ctxA[r][k] fp16 = max(ctx_i, ctx_j), r = ii*8 + jj, stride 132 words
    const float* ctxb = g_ctx + (size_t)b * Kk * Hh;
    for (int idx = tid; idx < 64 * 64; idx += 256) {
        int r = idx >> 6, k4 = (idx & 63) << 2;
        float4 va = *(const float4*)&ctxb[(I0 + (r >> 3)) * 256 + k4];
        float4 vb = *(const float4*)&ctxb[(J0 + (r & 7)) * 256 + k4];
        __half2 h0 = __floats2half2_rn(fmaxf(va.x, vb.x), fmaxf(va.y, vb.y));
        __half2 h1 = __floats2half2_rn(fmaxf(va.z, vb.z), fmaxf(va.w, vb.w));
        uint32_t* dst = &ctxA[r * 132 + (k4 >> 1)];
        dst[0] = *(uint32_t*)&h0;
        dst[1] = *(uint32_t*)&h1;
    }

    // ldmatrix lane offsets (words)
    int lrow = lane & 7;
    int lsel8 = (lane >> 3) & 1;
    int lsel16 = lane >> 4;
    uint32_t aoff1[2], aoff2[2], boff1[2], boff2[4];
#pragma unroll
    for (int mt = 0; mt < 2; ++mt) {
        int r = wm * 32 + mt * 16 + lrow + lsel8 * 8;
        aoff1[mt] = (uint32_t)(r * 132 + lsel16 * 4);
        aoff2[mt] = (uint32_t)(r * 68 + lsel16 * 4);
    }
#pragma unroll
    for (int p = 0; p < 2; ++p)
        boff1[p] = (uint32_t)((wn * 32 + p * 16 + lsel16 * 8 + lrow) * 132 + lsel8 * 4);
#pragma unroll
    for (int p = 0; p < 4; ++p)
        boff2[p] = (uint32_t)((wn * 64 + p * 16 + lsel16 * 8 + lrow) * 68 + lsel8 * 4);

    float oacc[2][8][4];
#pragma unroll
    for (int mt = 0; mt < 2; ++mt)
#pragma unroll
        for (int nt = 0; nt < 8; ++nt)
#pragma unroll
            for (int r = 0; r < 4; ++r) oacc[mt][nt][r] = 0.f;

    const int jj = g;

    for (int c = 0; c < NCH; ++c) {
        int fc  = c * F;
        int fcn = (c < NCH - 1) ? fc + F : 0;

        cp_wait<1>();          // G1_c landed (w1)
        __syncthreads();       // + ctxA/hs hazards

        float2 phv[2][2][4], ptv[4];
#pragma unroll
        for (int mt = 0; mt < 2; ++mt) {
            int ii = 4 * wm + 2 * mt;
#pragma unroll
            for (int nt = 0; nt < 4; ++nt) {
                int col = fc + wn * 32 + nt * 8 + 2 * q;
                phv[mt][0][nt] = __ldg((const float2*)&phbase[(size_t)ii * FFN + col]);
                phv[mt][1][nt] = __ldg((const float2*)&phbase[(size_t)(ii + 1) * FFN + col]);
            }
        }
#pragma unroll
        for (int nt = 0; nt < 4; ++nt)
            ptv[nt] = __ldg((const float2*)&ptbase[(size_t)jj * FFN + fc + wn * 32 + nt * 8 + 2 * q]);

        // ---- GEMM1: [64 x 128] = ctxA[64x256] @ w1^T, 16 k16-steps ----
        float c1[2][4][4];
#pragma unroll
        for (int mt = 0; mt < 2; ++mt)
#pragma unroll
            for (int nt = 0; nt < 4; ++nt)
#pragma unroll
                for (int r = 0; r < 4; ++r) c1[mt][nt][r] = 0.f;

#pragma unroll
        for (int i = 0; i < 16; ++i) {
            int kb = i * 8;
            uint32_t a[2][4], bp[2][4];
#pragma unroll
            for (int mt = 0; mt < 2; ++mt) ldsm4(a[mt], ctxA_u + (aoff1[mt] + kb) * 4);
#pragma unroll
            for (int p = 0; p < 2; ++p) ldsm4(bp[p], w1b_u + (boff1[p] + kb) * 4);
#pragma unroll
            for (int mt = 0; mt < 2; ++mt)
#pragma unroll
                for (int nt = 0; nt < 4; ++nt) {
                    uint32_t bb[2] = { bp[nt >> 1][(nt & 1) * 2], bp[nt >> 1][(nt & 1) * 2 + 1] };
                    mma16(c1[mt][nt], a[mt], bb);
                }
        }

        // epilogue: h = relu(C1 + Ph_i + Pt_j) -> hs fp16 (stride 68 words)
#pragma unroll
        for (int mt = 0; mt < 2; ++mt) {
#pragma unroll
            for (int nt = 0; nt < 4; ++nt) {
                int r0 = wm * 32 + mt * 16 + g;
                int r1 = r0 + 8;
                int c0 = wn * 32 + nt * 8 + 2 * q;
                float2 ph0 = phv[mt][0][nt];
                float2 ph1 = phv[mt][1][nt];
                float2 pt  = ptv[nt];
                float h00 = fmaxf(c1[mt][nt][0] + ph0.x + pt.x, 0.f);
                float h01 = fmaxf(c1[mt][nt][1] + ph0.y + pt.y, 0.f);
                float h10 = fmaxf(c1[mt][nt][2] + ph1.x + pt.x, 0.f);
                float h11 = fmaxf(c1[mt][nt][3] + ph1.y + pt.y, 0.f);
                __half2 p0 = __floats2half2_rn(h00, h01);
                __half2 p1 = __floats2half2_rn(h10, h11);
                hs[r0 * 68 + (c0 >> 1)] = *(uint32_t*)&p0;
                hs[r1 * 68 + (c0 >> 1)] = *(uint32_t*)&p1;
            }
        }

        cp_wait<0>();          // G2_c landed (w2)
        __syncthreads();       // hs visible; w1 free
        stage_w1(fcn); cp_commit();   // G1_{c+1} (overlaps GEMM2)

        // ---- GEMM2: out[64x256] += hs[64x128] @ w2^T, 8 k16-steps ----
#pragma unroll
        for (int i = 0; i < 8; ++i) {
            int kb = i * 8;
            uint32_t a[2][4], bp[4][4];
#pragma unroll
            for (int mt = 0; mt < 2; ++mt) ldsm4(a[mt], hs_u + (aoff2[mt] + kb) * 4);
#pragma unroll
            for (int p = 0; p < 4; ++p) ldsm4(bp[p], w2s_u + (boff2[p] + kb) * 4);
#pragma unroll
            for (int mt = 0; mt < 2; ++mt)
#pragma unroll
                for (int nt = 0; nt < 8; ++nt) {
                    uint32_t bb[2] = { bp[nt >> 1][(nt & 1) * 2], bp[nt >> 1][(nt & 1) * 2 + 1] };
                    mma16(oacc[mt][nt], a[mt], bb);
                }
        }

        __syncthreads();       // everyone done reading w2s + hs
        stage_w2(fcn); cp_commit();   // G2_{c+1}
    }

    // write output: out[b][i*64+j][h] + b2
    float* outp = out + (size_t)b * (Kk * Kk * Hh);
#pragma unroll
    for (int mt = 0; mt < 2; ++mt) {
#pragma unroll
        for (int nt = 0; nt < 8; ++nt) {
            int r0 = wm * 32 + mt * 16 + g;
            int r1 = r0 + 8;
            int c0 = wn * 64 + nt * 8 + 2 * q;
            float2 bv = __ldg((const float2*)&b2[c0]);
            int p0 = (I0 + (r0 >> 3)) * 64 + (J0 + (r0 & 7));
            int p1 = (I0 + (r1 >> 3)) * 64 + (J0 + (r1 & 7));
            float2 v0 = make_float2(oacc[mt][nt][0] + bv.x, oacc[mt][nt][1] + bv.y);
            float2 v1 = make_float2(oacc[mt][nt][2] + bv.x, oacc[mt][nt][3] + bv.y);
            *(float2*)&outp[(size_t)p0 * 256 + c0] = v0;
            *(float2*)&outp[(size_t)p1 * 256 + c0] = v1;
        }
    }
}

// ---------------------------------------------------------------------------
extern "C" void kernel_launch(void* const* d_in, const int* in_sizes, int n_in,
                              void* d_out, int out_size) {
    const float* cand = (const float*)d_in[0];
    const float* tok  = (const float*)d_in[1];
    const float* W1   = (const float*)d_in[2];
    const float* b1   = (const float*)d_in[3];
    const float* W2   = (const float*)d_in[4];
    const float* b2   = (const float*)d_in[5];
    const int*   ids  = (const int*)d_in[6];
    float* out = (float*)d_out;

    ctx_kernel<<<Bb * Kk, Hh>>>(tok, ids);
    w1t_kernel<<<dim3(FFN / 32, 768 / 32), dim3(32, 8)>>>(W1);
    w2t_kernel<<<dim3(Hh / 32, FFN / 32), dim3(32, 8)>>>(W2);
    candh_kernel<<<128, 256>>>(cand);

    cudaFuncSetAttribute(phpt_kernel, cudaFuncAttributeMaxDynamicSharedMemorySize, PHPT_SMEM);
    phpt_kernel<<<dim3(FFN / 128, (Bb * Kk) / 64, 2), 256, PHPT_SMEM>>>(b1, nullptr);

    const int smem_bytes = SMEM_WORDS * 4;  // 188416
    cudaFuncSetAttribute(pair_kernel, cudaFuncAttributeMaxDynamicSharedMemorySize, smem_bytes);
    pair_kernel<<<dim3(8, 8, 8), 256, smem_bytes>>>(b2, out);
}